// round 3
// baseline (speedup 1.0000x reference)
#include <cuda_runtime.h>
#include <cuda_bf16.h>

#define NE 20000
#define NN 1000

// permuted row order: m=0 rows(5), +1(4), -1(4), +2(3), -2(3)
__constant__ int c_PERM[19]   = {0,2,6,11,16, 3,7,12,17, 1,5,10,15, 8,13,18, 4,9,14};
__constant__ int c_RADOFF[19] = {0,128,256,384,512, 640,768,896,1024, 640,768,896,1024,
                                 1152,1280,1408, 1152,1280,1408};

// ----------------- scratch (__device__ globals; no runtime alloc) -----------
__device__ __align__(16) float g_hid [(size_t)NE*64];
__device__ __align__(16) float g_rad [(size_t)NE*1536];
__device__ __align__(16) float g_sm  [(size_t)NE*2432];   // wigner out, permuted, rad-scaled
__device__ __align__(16) float g_tmp0[(size_t)NE*896];    // conv1 gemm0 out (alpha|gate|m0)
__device__ __align__(16) float g_h1  [(size_t)NE*1216];   // conv1 out rows 5..18 (64/row)
__device__ __align__(16) float g_h2  [(size_t)NE*1216];   // grid-stage out (19x64 permuted)
__device__ __align__(16) float g_h3  [(size_t)NE*2432];   // conv2 out (19x128 permuted)
__device__ __align__(16) float g_alf [(size_t)NE*8];
__device__ unsigned int        g_amax[NN*8];
__device__ float               g_den [NN*8];
__device__ __align__(16) float g_node[(size_t)NN*3200];

// ----------------- helpers --------------------------------------------------
__device__ __forceinline__ float sigmoidf_(float x){ return 1.f/(1.f+__expf(-x)); }
__device__ __forceinline__ float siluf_(float x){ return x*sigmoidf_(x); }
__device__ __forceinline__ float slrelu_(float x){ return 0.6f*x + 0.4f*x*(2.f*sigmoidf_(x)-1.f); }

// packed dual-fp32 FMA: d = a*b + d  (SASS FFMA2 — 2x fp32 throughput)
__device__ __forceinline__ void fma2(unsigned long long &d,
                                     unsigned long long a, unsigned long long b){
    asm("fma.rn.f32x2 %0, %1, %2, %0;" : "+l"(d) : "l"(a), "l"(b));
}
#define SGN2 0x8000000080000000ULL

// reduce over 64 threads (2 warps), blockDim==64
__device__ __forceinline__ float red64(float v, float* sbuf, int t){
    #pragma unroll
    for (int o=16;o;o>>=1) v += __shfl_xor_sync(0xffffffffu, v, o);
    if ((t&31)==0) sbuf[t>>5] = v;
    __syncthreads();
    float r = sbuf[0]+sbuf[1];
    __syncthreads();
    return r;
}

// ----------------- init -----------------------------------------------------
__global__ void k_init(float* node, unsigned int* amax, float* den){
    int i = blockIdx.x*256 + threadIdx.x;
    if (i < NN*3200) node[i] = 0.f;
    if (i < NN*8) { amax[i] = 0u; den[i] = 0.f; }
}

// ----------------- radial layers 1+2 (LN + silu) ----------------------------
__global__ void k_radial(const float* __restrict__ ed,
                         const float* __restrict__ w1, const float* __restrict__ b1,
                         const float* __restrict__ g1, const float* __restrict__ be1,
                         const float* __restrict__ w2, const float* __restrict__ b2,
                         const float* __restrict__ g2, const float* __restrict__ be2,
                         float* __restrict__ outp)
{
    __shared__ float w1t[64*64], w2t[64*64];
    __shared__ float xin[64], hmid[64];
    __shared__ float sbuf[2];
    int t = threadIdx.x; // 64
    for (int i = t; i < 4096; i += 64) {
        int r = i >> 6, c = i & 63;
        w1t[c*64 + r] = w1[i];
        w2t[c*64 + r] = w2[i];
    }
    __syncthreads();
    for (int e = blockIdx.x; e < NE; e += gridDim.x) {
        xin[t] = ed[(size_t)e*64 + t];
        __syncthreads();
        float acc = b1[t];
        #pragma unroll 8
        for (int k = 0; k < 64; k++) acc += xin[k]*w1t[k*64+t];
        float mu = red64(acc, sbuf, t) * (1.f/64.f);
        float d = acc - mu;
        float var = red64(d*d, sbuf, t) * (1.f/64.f);
        float v = d*rsqrtf(var+1e-5f)*g1[t] + be1[t];
        hmid[t] = siluf_(v);
        __syncthreads();
        acc = b2[t];
        #pragma unroll 8
        for (int k = 0; k < 64; k++) acc += hmid[k]*w2t[k*64+t];
        mu = red64(acc, sbuf, t) * (1.f/64.f);
        d = acc - mu;
        var = red64(d*d, sbuf, t) * (1.f/64.f);
        v = d*rsqrtf(var+1e-5f)*g2[t] + be2[t];
        outp[(size_t)e*64 + t] = siluf_(v);
        __syncthreads();
    }
}

// ======== real GEMM (f32x2 packed): C[M,N] = A[M,K] @ W[N,K]^T + bias ========
// 128x64 tile, 256 threads, per-thread 8 rows x 4 cols (row-pair packed accum)
__global__ void __launch_bounds__(256) k_gemm2(
        const float* __restrict__ A, int lda,
        const float* __restrict__ W, const float* __restrict__ bias,
        float* __restrict__ C, int ldc, int M, int N, int K)
{
    __shared__ float As[16][128];
    __shared__ float Bs[16][128];   // duplicated (b,b) pairs
    const int tid = threadIdx.x;
    const int bm = blockIdx.x*128, bn = blockIdx.y*64;
    const int tx = tid & 15, ty = tid >> 4;
    const int arow = tid >> 1, aq = tid & 1;
    const int brow = tid >> 2, bq = tid & 3;
    unsigned long long acc[4][4];
    #pragma unroll
    for (int i=0;i<4;i++){
        #pragma unroll
        for (int j=0;j<4;j++) acc[i][j]=0ull;
    }
    const bool aval = (bm + arow) < M;
    const float* Ap = A + (size_t)(bm+arow)*lda + aq*8;
    const float* Wp = W + (size_t)(bn+brow)*K + bq*4;
    for (int k0 = 0; k0 < K; k0 += 16) {
        float4 a0 = make_float4(0.f,0.f,0.f,0.f), a1 = a0;
        if (aval) { a0 = *(const float4*)(Ap+k0); a1 = *(const float4*)(Ap+k0+4); }
        float4 bv = *(const float4*)(Wp+k0);
        __syncthreads();
        As[aq*8+0][arow]=a0.x; As[aq*8+1][arow]=a0.y; As[aq*8+2][arow]=a0.z; As[aq*8+3][arow]=a0.w;
        As[aq*8+4][arow]=a1.x; As[aq*8+5][arow]=a1.y; As[aq*8+6][arow]=a1.z; As[aq*8+7][arow]=a1.w;
        int b2 = 2*brow;
        Bs[bq*4+0][b2]=bv.x; Bs[bq*4+0][b2+1]=bv.x;
        Bs[bq*4+1][b2]=bv.y; Bs[bq*4+1][b2+1]=bv.y;
        Bs[bq*4+2][b2]=bv.z; Bs[bq*4+2][b2+1]=bv.z;
        Bs[bq*4+3][b2]=bv.w; Bs[bq*4+3][b2+1]=bv.w;
        __syncthreads();
        #pragma unroll
        for (int k=0;k<16;k++) {
            ulonglong2 aA = *(const ulonglong2*)&As[k][ty*8];
            ulonglong2 aB = *(const ulonglong2*)&As[k][ty*8+4];
            ulonglong2 bA = *(const ulonglong2*)&Bs[k][tx*8];
            ulonglong2 bB = *(const ulonglong2*)&Bs[k][tx*8+4];
            fma2(acc[0][0], aA.x, bA.x); fma2(acc[0][1], aA.x, bA.y);
            fma2(acc[0][2], aA.x, bB.x); fma2(acc[0][3], aA.x, bB.y);
            fma2(acc[1][0], aA.y, bA.x); fma2(acc[1][1], aA.y, bA.y);
            fma2(acc[1][2], aA.y, bB.x); fma2(acc[1][3], aA.y, bB.y);
            fma2(acc[2][0], aB.x, bA.x); fma2(acc[2][1], aB.x, bA.y);
            fma2(acc[2][2], aB.x, bB.x); fma2(acc[2][3], aB.x, bB.y);
            fma2(acc[3][0], aB.y, bA.x); fma2(acc[3][1], aB.y, bA.y);
            fma2(acc[3][2], aB.y, bB.x); fma2(acc[3][3], aB.y, bB.y);
        }
    }
    float4 bb = *(const float4*)(bias + bn + tx*4);
    #pragma unroll
    for (int r = 0; r < 8; r++) {
        int m = bm + ty*8 + r;
        if (m < M) {
            int ip = r >> 1, h = r & 1;
            float2 v0 = *(float2*)&acc[ip][0];
            float2 v1 = *(float2*)&acc[ip][1];
            float2 v2 = *(float2*)&acc[ip][2];
            float2 v3 = *(float2*)&acc[ip][3];
            float4 o;
            o.x = (h? v0.y : v0.x) + bb.x;
            o.y = (h? v1.y : v1.x) + bb.y;
            o.z = (h? v2.y : v2.x) + bb.z;
            o.w = (h? v3.y : v3.x) + bb.w;
            *(float4*)(C + (size_t)m*ldc + bn + tx*4) = o;
        }
    }
}

// ==== complex GEMM (f32x2 packed): (Cp + iCm) = (Are + iAim) @ (Wr + iWi)^T ==
__global__ void __launch_bounds__(256) k_cgemm2(
        const float* __restrict__ Are, const float* __restrict__ Aim, int lda,
        const float* __restrict__ W, int wioff,
        float* __restrict__ Cp, float* __restrict__ Cm, int ldc,
        int M, int N, int K)
{
    __shared__ float Ars[16][128], Ais[16][128];
    __shared__ float Wrs[16][128], Wis[16][128];   // duplicated pairs
    const int tid = threadIdx.x;
    const int bm = blockIdx.x*128, bn = blockIdx.y*64;
    const int tx = tid & 15, ty = tid >> 4;
    const int arow = tid >> 1, aq = tid & 1;
    const int brow = tid >> 2, bq = tid & 3;
    unsigned long long accr[4][4], acci[4][4];
    #pragma unroll
    for (int i=0;i<4;i++){
        #pragma unroll
        for (int j=0;j<4;j++){ accr[i][j]=0ull; acci[i][j]=0ull; }
    }
    const bool aval = (bm + arow) < M;
    const float* Arp = Are + (size_t)(bm+arow)*lda + aq*8;
    const float* Aip = Aim + (size_t)(bm+arow)*lda + aq*8;
    const float* Wrp = W + (size_t)(bn+brow)*K + bq*4;
    const float* Wip = W + (size_t)wioff + (size_t)(bn+brow)*K + bq*4;
    for (int k0 = 0; k0 < K; k0 += 16) {
        float4 r0 = make_float4(0.f,0.f,0.f,0.f), r1 = r0, i0 = r0, i1 = r0;
        if (aval) {
            r0 = *(const float4*)(Arp+k0); r1 = *(const float4*)(Arp+k0+4);
            i0 = *(const float4*)(Aip+k0); i1 = *(const float4*)(Aip+k0+4);
        }
        float4 wr = *(const float4*)(Wrp+k0);
        float4 wi = *(const float4*)(Wip+k0);
        __syncthreads();
        Ars[aq*8+0][arow]=r0.x; Ars[aq*8+1][arow]=r0.y; Ars[aq*8+2][arow]=r0.z; Ars[aq*8+3][arow]=r0.w;
        Ars[aq*8+4][arow]=r1.x; Ars[aq*8+5][arow]=r1.y; Ars[aq*8+6][arow]=r1.z; Ars[aq*8+7][arow]=r1.w;
        Ais[aq*8+0][arow]=i0.x; Ais[aq*8+1][arow]=i0.y; Ais[aq*8+2][arow]=i0.z; Ais[aq*8+3][arow]=i0.w;
        Ais[aq*8+4][arow]=i1.x; Ais[aq*8+5][arow]=i1.y; Ais[aq*8+6][arow]=i1.z; Ais[aq*8+7][arow]=i1.w;
        int b2 = 2*brow;
        Wrs[bq*4+0][b2]=wr.x; Wrs[bq*4+0][b2+1]=wr.x;
        Wrs[bq*4+1][b2]=wr.y; Wrs[bq*4+1][b2+1]=wr.y;
        Wrs[bq*4+2][b2]=wr.z; Wrs[bq*4+2][b2+1]=wr.z;
        Wrs[bq*4+3][b2]=wr.w; Wrs[bq*4+3][b2+1]=wr.w;
        Wis[bq*4+0][b2]=wi.x; Wis[bq*4+0][b2+1]=wi.x;
        Wis[bq*4+1][b2]=wi.y; Wis[bq*4+1][b2+1]=wi.y;
        Wis[bq*4+2][b2]=wi.z; Wis[bq*4+2][b2+1]=wi.z;
        Wis[bq*4+3][b2]=wi.w; Wis[bq*4+3][b2+1]=wi.w;
        __syncthreads();
        #pragma unroll
        for (int k=0;k<16;k++) {
            ulonglong2 rA = *(const ulonglong2*)&Ars[k][ty*8];
            ulonglong2 rB = *(const ulonglong2*)&Ars[k][ty*8+4];
            ulonglong2 iA = *(const ulonglong2*)&Ais[k][ty*8];
            ulonglong2 iB = *(const ulonglong2*)&Ais[k][ty*8+4];
            ulonglong2 wA = *(const ulonglong2*)&Wrs[k][tx*8];
            ulonglong2 wB = *(const ulonglong2*)&Wrs[k][tx*8+4];
            ulonglong2 vA = *(const ulonglong2*)&Wis[k][tx*8];
            ulonglong2 vB = *(const ulonglong2*)&Wis[k][tx*8+4];
            unsigned long long ar[4] = {rA.x, rA.y, rB.x, rB.y};
            unsigned long long ai[4] = {iA.x, iA.y, iB.x, iB.y};
            unsigned long long wrj[4] = {wA.x, wA.y, wB.x, wB.y};
            unsigned long long wij[4] = {vA.x, vA.y, vB.x, vB.y};
            #pragma unroll
            for (int ip=0; ip<4; ip++) {
                unsigned long long nai = ai[ip] ^ SGN2;
                #pragma unroll
                for (int j=0;j<4;j++) {
                    fma2(accr[ip][j], ar[ip],  wrj[j]);
                    fma2(accr[ip][j], nai,     wij[j]);
                    fma2(acci[ip][j], ai[ip],  wrj[j]);
                    fma2(acci[ip][j], ar[ip],  wij[j]);
                }
            }
        }
    }
    #pragma unroll
    for (int r = 0; r < 8; r++) {
        int m = bm + ty*8 + r;
        if (m < M) {
            int ip = r >> 1, h = r & 1;
            float4 op, om;
            {
                float2 v0 = *(float2*)&accr[ip][0];
                float2 v1 = *(float2*)&accr[ip][1];
                float2 v2 = *(float2*)&accr[ip][2];
                float2 v3 = *(float2*)&accr[ip][3];
                op.x = h? v0.y : v0.x; op.y = h? v1.y : v1.x;
                op.z = h? v2.y : v2.x; op.w = h? v3.y : v3.x;
            }
            {
                float2 v0 = *(float2*)&acci[ip][0];
                float2 v1 = *(float2*)&acci[ip][1];
                float2 v2 = *(float2*)&acci[ip][2];
                float2 v3 = *(float2*)&acci[ip][3];
                om.x = h? v0.y : v0.x; om.y = h? v1.y : v1.x;
                om.z = h? v2.y : v2.x; om.w = h? v3.y : v3.x;
            }
            *(float4*)(Cp + (size_t)m*ldc + bn + tx*4) = op;
            *(float4*)(Cm + (size_t)m*ldc + bn + tx*4) = om;
        }
    }
}

// ---------- wigner: msg = perm(wigner @ [x_src|x_dst]) * rad ----------------
__global__ void k_wigner(const float* __restrict__ x, const int* __restrict__ ei,
                         const float* __restrict__ wig, const float* __restrict__ rad,
                         float* __restrict__ sm)
{
    __shared__ float msg[25][128];
    __shared__ float wg[19][25];
    int e = blockIdx.x;
    int t = threadIdx.x; // 128
    int src = ei[e], dst = ei[NE + e];
    const float* xs = x + (size_t)src*1600;
    const float* xd = x + (size_t)dst*1600;
    int c = t & 63;
    if (t < 64) { for (int j=0;j<25;j++) msg[j][t] = xs[j*64+c]; }
    else        { for (int j=0;j<25;j++) msg[j][t] = xd[j*64+c]; }
    for (int i = t; i < 475; i += 128) {
        int p = i/25, j = i%25;
        wg[p][j] = wig[(size_t)e*475 + (size_t)c_PERM[p]*25 + j];
    }
    __syncthreads();
    const float* re = rad + (size_t)e*1536;
    float* so = sm + (size_t)e*2432;
    #pragma unroll
    for (int p = 0; p < 19; p++) {
        float acc = 0.f;
        #pragma unroll
        for (int j = 0; j < 25; j++) acc += wg[p][j]*msg[j][t];
        so[p*128 + t] = acc * re[c_RADOFF[p] + t];
    }
}

// ---------- grid stage: silu-gated S2 pointwise -----------------------------
__global__ void k_grid(const float* __restrict__ tmp0, const float* __restrict__ h1,
                       const float* __restrict__ tgrid, const float* __restrict__ fgrid,
                       float* __restrict__ h2)
{
    __shared__ float tg[100][20];
    __shared__ float fg[100][20];
    __shared__ float h[2][19][64];
    int t = threadIdx.x; // 128
    for (int i = t; i < 1900; i += 128) {
        int ba = i / 19, p = i % 19;
        tg[ba][p] = tgrid[ba*19 + c_PERM[p]];
        fg[ba][p] = fgrid[ba*19 + c_PERM[p]];
    }
    int el = t >> 6, c = t & 63;
    int e = blockIdx.x*2 + el;
    const float* t0 = tmp0 + (size_t)e*896;
    #pragma unroll
    for (int p = 0; p < 5; p++) h[el][p][c] = t0[576 + p*64 + c];
    const float* hh = h1 + (size_t)e*1216;
    #pragma unroll
    for (int p = 5; p < 19; p++) h[el][p][c] = hh[p*64 + c];
    __syncthreads();
    float s2[19];
    #pragma unroll
    for (int p=0;p<19;p++) s2[p]=0.f;
    for (int ba = 0; ba < 100; ba++) {
        float g = 0.f;
        #pragma unroll
        for (int p = 0; p < 19; p++) g += tg[ba][p]*h[el][p][c];
        g = siluf_(g);
        #pragma unroll
        for (int p = 0; p < 19; p++) s2[p] += fg[ba][p]*g;
    }
    float* o = h2 + (size_t)e*1216;
    o[c] = siluf_(t0[512 + c]);          // row 0 := silu(gate)
    #pragma unroll
    for (int p = 1; p < 19; p++) o[p*64 + c] = s2[p];
}

// ---------- alpha: LN + smooth-leaky-relu + dot, atomicMax ------------------
__global__ void k_alpha1(const float* __restrict__ tmp0, const int* __restrict__ ei,
                         const float* __restrict__ lng, const float* __restrict__ lnb,
                         const float* __restrict__ adot,
                         float* __restrict__ alpha, unsigned int* __restrict__ amax)
{
    int e = blockIdx.x;
    int w = threadIdx.x >> 5, lane = threadIdx.x & 31; // 8 warps = 8 heads
    const float* a = tmp0 + (size_t)e*896 + w*64;
    float v0 = a[lane], v1 = a[lane+32];
    float s = v0+v1;
    #pragma unroll
    for (int o=16;o;o>>=1) s += __shfl_xor_sync(0xffffffffu, s, o);
    float mu = s * (1.f/64.f);
    float d0=v0-mu, d1=v1-mu;
    float q = d0*d0+d1*d1;
    #pragma unroll
    for (int o=16;o;o>>=1) q += __shfl_xor_sync(0xffffffffu, q, o);
    float rstd = rsqrtf(q*(1.f/64.f) + 1e-5f);
    float x0 = slrelu_(d0*rstd*lng[lane]+lnb[lane]);
    float x1 = slrelu_(d1*rstd*lng[lane+32]+lnb[lane+32]);
    float p = x0*adot[w*64+lane] + x1*adot[w*64+lane+32];
    #pragma unroll
    for (int o=16;o;o>>=1) p += __shfl_xor_sync(0xffffffffu, p, o);
    if (lane == 0) {
        alpha[e*8+w] = p;
        int dst = ei[NE + e];
        unsigned int enc = __float_as_uint(p);
        enc = (enc & 0x80000000u) ? ~enc : (enc | 0x80000000u);
        atomicMax(&amax[dst*8+w], enc);
    }
}

__global__ void k_alpha2(float* __restrict__ alpha, const int* __restrict__ ei,
                         const unsigned int* __restrict__ amax, float* __restrict__ den)
{
    int i = blockIdx.x*256 + threadIdx.x;
    if (i >= NE*8) return;
    int e = i >> 3, h = i & 7;
    int dst = ei[NE + e];
    unsigned int u = amax[dst*8+h];
    float m = (u & 0x80000000u) ? __uint_as_float(u & 0x7FFFFFFFu) : __uint_as_float(~u);
    float ex = __expf(alpha[i] - m);
    alpha[i] = ex;
    atomicAdd(&den[dst*8+h], ex);
}

// ---------- attention weight + wigner_inv + segment-sum ---------------------
__global__ void k_attn(const float* __restrict__ h3, const float* __restrict__ winv,
                       const float* __restrict__ alpha, const float* __restrict__ den,
                       const int* __restrict__ ei, float* __restrict__ node)
{
    __shared__ float m[19][128];
    __shared__ float wi[25][20];
    __shared__ float wt[8];
    int e = blockIdx.x, t = threadIdx.x; // 128
    int dst = ei[NE + e];
    if (t < 8) wt[t] = alpha[e*8+t] / (den[dst*8+t] + 1e-16f);
    for (int i = t; i < 475; i += 128) {
        int r = i/19, p = i%19;
        wi[r][p] = winv[(size_t)e*475 + r*19 + c_PERM[p]];
    }
    __syncthreads();
    const float* hh = h3 + (size_t)e*2432;
    float w = wt[t >> 4];
    #pragma unroll
    for (int p = 0; p < 19; p++) m[p][t] = hh[p*128 + t] * w;
    __syncthreads();
    float* no = node + (size_t)dst*3200;
    #pragma unroll
    for (int r = 0; r < 25; r++) {
        float acc = 0.f;
        #pragma unroll
        for (int p = 0; p < 19; p++) acc += wi[r][p]*m[p][t];
        atomicAdd(&no[r*128 + t], acc);
    }
}

// ---------- output projection ----------------------------------------------
__global__ void k_proj(const float* __restrict__ node, const float* __restrict__ pw,
                       const float* __restrict__ pb, float* __restrict__ outp)
{
    __shared__ float wt[128*65];
    int bid = blockIdx.x;      // n*5 + l
    int n = bid / 5, l = bid % 5;
    int t = threadIdx.x;       // 64
    for (int i = t; i < 8192; i += 64) {
        int o = i >> 7, c = i & 127;
        wt[c*65 + o] = pw[l*8192 + i];
    }
    __syncthreads();
    int i0 = l*l, i1 = (l+1)*(l+1);
    for (int i = i0; i < i1; i++) {
        const float* nr = node + (size_t)n*3200 + i*128;
        float acc = (i == 0) ? pb[t] : 0.f;
        #pragma unroll 8
        for (int c = 0; c < 128; c++) acc += nr[c] * wt[c*65 + t];
        outp[(size_t)n*1600 + i*64 + t] = acc;
    }
}

// ----------------------------------------------------------------------------
extern "C" void kernel_launch(void* const* d_in, const int* in_sizes, int n_in,
                              void* d_out, int out_size)
{
    const float* x    = (const float*)d_in[0];
    const float* ed   = (const float*)d_in[1];
    const int*   ei   = (const int*)  d_in[2];
    const float* wig  = (const float*)d_in[3];
    const float* winv = (const float*)d_in[4];
    const float* tgr  = (const float*)d_in[5];
    const float* fgr  = (const float*)d_in[6];
    const float* rw1  = (const float*)d_in[7];
    const float* rb1  = (const float*)d_in[8];
    const float* rg1  = (const float*)d_in[9];
    const float* rbe1 = (const float*)d_in[10];
    const float* rw2  = (const float*)d_in[11];
    const float* rb2  = (const float*)d_in[12];
    const float* rg2  = (const float*)d_in[13];
    const float* rbe2 = (const float*)d_in[14];
    const float* rw3  = (const float*)d_in[15];
    const float* rb3  = (const float*)d_in[16];
    const float* c1w0 = (const float*)d_in[17];
    const float* c1b0 = (const float*)d_in[18];
    const float* c1w1 = (const float*)d_in[19];
    const float* c1w2 = (const float*)d_in[20];
    const float* c2w0 = (const float*)d_in[21];
    const float* c2b0 = (const float*)d_in[22];
    const float* c2w1 = (const float*)d_in[23];
    const float* c2w2 = (const float*)d_in[24];
    const float* alng = (const float*)d_in[25];
    const float* alnb = (const float*)d_in[26];
    const float* adot = (const float*)d_in[27];
    const float* pw   = (const float*)d_in[28];
    const float* pb   = (const float*)d_in[29];
    float* outp = (float*)d_out;

    void* p;
    cudaGetSymbolAddress(&p, g_hid);  float* hid  = (float*)p;
    cudaGetSymbolAddress(&p, g_rad);  float* rad  = (float*)p;
    cudaGetSymbolAddress(&p, g_sm);   float* sm   = (float*)p;
    cudaGetSymbolAddress(&p, g_tmp0); float* tmp0 = (float*)p;
    cudaGetSymbolAddress(&p, g_h1);   float* h1   = (float*)p;
    cudaGetSymbolAddress(&p, g_h2);   float* h2   = (float*)p;
    cudaGetSymbolAddress(&p, g_h3);   float* h3   = (float*)p;
    cudaGetSymbolAddress(&p, g_alf);  float* alf  = (float*)p;
    cudaGetSymbolAddress(&p, g_amax); unsigned int* amax = (unsigned int*)p;
    cudaGetSymbolAddress(&p, g_den);  float* den  = (float*)p;
    cudaGetSymbolAddress(&p, g_node); float* node = (float*)p;

    const int MB = (NE + 127) / 128;   // 157

    k_init<<<(NN*3200 + 255)/256, 256>>>(node, amax, den);
    k_radial<<<512, 64>>>(ed, rw1, rb1, rg1, rbe1, rw2, rb2, rg2, rbe2, hid);
    k_gemm2<<<dim3(MB, 24), 256>>>(hid, 64, rw3, rb3, rad, 1536, NE, 1536, 64);
    k_wigner<<<NE, 128>>>(x, ei, wig, rad, sm);
    // conv1
    k_gemm2<<<dim3(MB, 14), 256>>>(sm, 2432, c1w0, c1b0, tmp0, 896, NE, 896, 640);
    k_cgemm2<<<dim3(MB, 4), 256>>>(sm+640,  sm+1152, 2432, c1w1, 256*512,
                                   h1+320, h1+576, 1216, NE, 256, 512);
    k_cgemm2<<<dim3(MB, 3), 256>>>(sm+1664, sm+2048, 2432, c1w2, 192*384,
                                   h1+832, h1+1024, 1216, NE, 192, 384);
    // grid nonlinearity
    k_grid<<<NE/2, 128>>>(tmp0, h1, tgr, fgr, h2);
    // conv2
    k_gemm2<<<dim3(MB, 10), 256>>>(h2, 1216, c2w0, c2b0, h3, 2432, NE, 640, 320);
    k_cgemm2<<<dim3(MB, 8), 256>>>(h2+320, h2+576, 1216, c2w1, 512*256,
                                   h3+640,  h3+1152, 2432, NE, 512, 256);
    k_cgemm2<<<dim3(MB, 6), 256>>>(h2+832, h2+1024, 1216, c2w2, 384*192,
                                   h3+1664, h3+2048, 2432, NE, 384, 192);
    // attention
    k_alpha1<<<NE, 256>>>(tmp0, ei, alng, alnb, adot, alf, amax);
    k_alpha2<<<(NE*8 + 255)/256, 256>>>(alf, ei, amax, den);
    k_attn<<<NE, 128>>>(h3, winv, alf, den, ei, node);
    // projection
    k_proj<<<NN*5, 64>>>(node, pw, pb, outp);
}

// round 4
// speedup vs baseline: 1.6416x; 1.6416x over previous
#include <cuda_runtime.h>
#include <cuda_bf16.h>

#define NE 20000
#define NN 1000

// permuted row order: m=0 rows(5), +1(4), -1(4), +2(3), -2(3)
__constant__ int c_PERM[19]   = {0,2,6,11,16, 3,7,12,17, 1,5,10,15, 8,13,18, 4,9,14};
__constant__ int c_RADOFF[19] = {0,128,256,384,512, 640,768,896,1024, 640,768,896,1024,
                                 1152,1280,1408, 1152,1280,1408};

// ----------------- scratch (__device__ globals; no runtime alloc) -----------
__device__ __align__(16) float g_hid [(size_t)NE*64];
__device__ __align__(16) float g_rad [(size_t)NE*1536];
__device__ __align__(16) float g_sm  [(size_t)NE*2432];   // wigner out, permuted, rad-scaled
__device__ __align__(16) float g_tmp0[(size_t)NE*896];    // conv1 gemm0 out (alpha|gate|m0)
__device__ __align__(16) float g_h1  [(size_t)NE*1216];   // conv1 out rows 5..18 (64/row)
__device__ __align__(16) float g_h2  [(size_t)NE*1216];   // grid-stage out (19x64 permuted)
__device__ __align__(16) float g_h3  [(size_t)NE*2432];   // conv2 out (19x128 permuted)
__device__ __align__(16) float g_alf [(size_t)NE*8];
__device__ unsigned int        g_amax[NN*8];
__device__ float               g_den [NN*8];
__device__ __align__(16) float g_node[(size_t)NN*3200];
// tf32-prepped weights (plain + complex-expanded), constexpr offsets below
__device__ __align__(16) float g_wp  [2514944];

// offsets into g_wp
#define WP_RAD   0
#define WP_C1G0  98304
#define WP_C1M1  671744
#define WP_C1M2  1196032
#define WP_C2G0  1490944
#define WP_C2M1  1695744
#define WP_C2M2  2220032

// ----------------- helpers --------------------------------------------------
__device__ __forceinline__ float sigmoidf_(float x){ return 1.f/(1.f+__expf(-x)); }
__device__ __forceinline__ float siluf_(float x){ return x*sigmoidf_(x); }
__device__ __forceinline__ float slrelu_(float x){ return 0.6f*x + 0.4f*x*(2.f*sigmoidf_(x)-1.f); }

__device__ __forceinline__ float tf32f_(float x){
    unsigned r; asm("cvt.rna.tf32.f32 %0, %1;" : "=r"(r) : "f"(x));
    return __uint_as_float(r);
}

// m16n8k8 tf32 mma, fp32 accumulate
__device__ __forceinline__ void mma8(float* d, const unsigned* a, const unsigned* b){
    asm("mma.sync.aligned.m16n8k8.row.col.f32.tf32.tf32.f32 "
        "{%0,%1,%2,%3}, {%4,%5,%6,%7}, {%8,%9}, {%0,%1,%2,%3};"
        : "+f"(d[0]), "+f"(d[1]), "+f"(d[2]), "+f"(d[3])
        : "r"(a[0]), "r"(a[1]), "r"(a[2]), "r"(a[3]), "r"(b[0]), "r"(b[1]));
}

// reduce over 64 threads (2 warps), blockDim==64
__device__ __forceinline__ float red64(float v, float* sbuf, int t){
    #pragma unroll
    for (int o=16;o;o>>=1) v += __shfl_xor_sync(0xffffffffu, v, o);
    if ((t&31)==0) sbuf[t>>5] = v;
    __syncthreads();
    float r = sbuf[0]+sbuf[1];
    __syncthreads();
    return r;
}

// ----------------- init -----------------------------------------------------
__global__ void k_init(float* node, unsigned int* amax, float* den){
    int i = blockIdx.x*256 + threadIdx.x;
    if (i < NN*3200) node[i] = 0.f;
    if (i < NN*8) { amax[i] = 0u; den[i] = 0.f; }
}

// ----------------- weight prep ----------------------------------------------
// plain: elementwise tf32 round
__global__ void k_cvtw(const float* __restrict__ w, float* __restrict__ o, int n){
    int i = blockIdx.x*256 + threadIdx.x;
    if (i < n) o[i] = tf32f_(w[i]);
}
// complex: w[(2N)xK] (rows 0..N-1 = Wr, N..2N-1 = Wi) ->
// wp[(2N)x(2K)]: row n = [Wr[n] | -Wi[n]], row N+n = [Wi[n] | Wr[n]]
__global__ void k_prepw(const float* __restrict__ w, float* __restrict__ wp, int N, int K){
    int i = blockIdx.x*256 + threadIdx.x;
    if (i >= N*K) return;
    int n = i / K, k = i % K;
    float wr = tf32f_(w[(size_t)n*K + k]);
    float wi = tf32f_(w[(size_t)(N+n)*K + k]);
    size_t row0 = (size_t)n*2*K, row1 = (size_t)(N+n)*2*K;
    wp[row0 + k]     = wr;
    wp[row0 + K + k] = -wi;
    wp[row1 + k]     = wi;
    wp[row1 + K + k] = wr;
}

// ----------------- radial layers 1+2 (LN + silu) ----------------------------
__global__ void k_radial(const float* __restrict__ ed,
                         const float* __restrict__ w1, const float* __restrict__ b1,
                         const float* __restrict__ g1, const float* __restrict__ be1,
                         const float* __restrict__ w2, const float* __restrict__ b2,
                         const float* __restrict__ g2, const float* __restrict__ be2,
                         float* __restrict__ outp)
{
    __shared__ float w1t[64*64], w2t[64*64];
    __shared__ float xin[64], hmid[64];
    __shared__ float sbuf[2];
    int t = threadIdx.x; // 64
    for (int i = t; i < 4096; i += 64) {
        int r = i >> 6, c = i & 63;
        w1t[c*64 + r] = w1[i];
        w2t[c*64 + r] = w2[i];
    }
    __syncthreads();
    for (int e = blockIdx.x; e < NE; e += gridDim.x) {
        xin[t] = ed[(size_t)e*64 + t];
        __syncthreads();
        float acc = b1[t];
        #pragma unroll 8
        for (int k = 0; k < 64; k++) acc += xin[k]*w1t[k*64+t];
        float mu = red64(acc, sbuf, t) * (1.f/64.f);
        float d = acc - mu;
        float var = red64(d*d, sbuf, t) * (1.f/64.f);
        float v = d*rsqrtf(var+1e-5f)*g1[t] + be1[t];
        hmid[t] = siluf_(v);
        __syncthreads();
        acc = b2[t];
        #pragma unroll 8
        for (int k = 0; k < 64; k++) acc += hmid[k]*w2t[k*64+t];
        mu = red64(acc, sbuf, t) * (1.f/64.f);
        d = acc - mu;
        var = red64(d*d, sbuf, t) * (1.f/64.f);
        v = d*rsqrtf(var+1e-5f)*g2[t] + be2[t];
        outp[(size_t)e*64 + t] = siluf_(v);
        __syncthreads();
    }
}

// ========== tf32 tensor-core GEMM: C[M,N] = A[M,K] @ W[N,K]^T (+bias) =======
// block tile 128x128, 8 warps (2x4), warp tile m64n32, BK=16.
// Requires: N % 128 == 0, K % 16 == 0. W already tf32-rounded. A rounded here.
__global__ void __launch_bounds__(256, 2) k_gemm_t(
        const float* __restrict__ A, int lda,
        const float* __restrict__ W,
        const float* __restrict__ bias,
        float* __restrict__ C, int ldc, int M, int N, int K)
{
    __shared__ float As[16][136];
    __shared__ float Bs[16][136];
    const int tid = threadIdx.x;
    const int bm = blockIdx.x*128, bn = blockIdx.y*128;
    const int wid = tid >> 5, lane = tid & 31;
    const int wm = wid & 1, wn = wid >> 1;        // 2 x 4 warps
    const int g = lane >> 2, q = lane & 3;
    const int srow = tid & 127, sq = tid >> 7;    // staging: row, k-half
    float acc[4][4][4];
    #pragma unroll
    for (int i=0;i<4;i++)
        #pragma unroll
        for (int j=0;j<4;j++)
            #pragma unroll
            for (int r=0;r<4;r++) acc[i][j][r] = 0.f;
    const bool aval = (bm + srow) < M;
    const float* Ap = A + (size_t)(bm+srow)*lda + sq*8;
    const float* Wp = W + (size_t)(bn+srow)*K + sq*8;

    for (int k0 = 0; k0 < K; k0 += 16) {
        float4 a0 = make_float4(0.f,0.f,0.f,0.f), a1 = a0;
        if (aval) { a0 = *(const float4*)(Ap + k0); a1 = *(const float4*)(Ap + k0 + 4); }
        float4 w0 = *(const float4*)(Wp + k0);
        float4 w1 = *(const float4*)(Wp + k0 + 4);
        __syncthreads();
        As[sq*8+0][srow]=tf32f_(a0.x); As[sq*8+1][srow]=tf32f_(a0.y);
        As[sq*8+2][srow]=tf32f_(a0.z); As[sq*8+3][srow]=tf32f_(a0.w);
        As[sq*8+4][srow]=tf32f_(a1.x); As[sq*8+5][srow]=tf32f_(a1.y);
        As[sq*8+6][srow]=tf32f_(a1.z); As[sq*8+7][srow]=tf32f_(a1.w);
        Bs[sq*8+0][srow]=w0.x; Bs[sq*8+1][srow]=w0.y;
        Bs[sq*8+2][srow]=w0.z; Bs[sq*8+3][srow]=w0.w;
        Bs[sq*8+4][srow]=w1.x; Bs[sq*8+5][srow]=w1.y;
        Bs[sq*8+6][srow]=w1.z; Bs[sq*8+7][srow]=w1.w;
        __syncthreads();
        #pragma unroll
        for (int ks = 0; ks < 16; ks += 8) {
            unsigned af[4][4];
            #pragma unroll
            for (int mt=0; mt<4; mt++){
                int mb = wm*64 + mt*16;
                af[mt][0] = __float_as_uint(As[ks+q  ][mb+g  ]);
                af[mt][1] = __float_as_uint(As[ks+q  ][mb+g+8]);
                af[mt][2] = __float_as_uint(As[ks+q+4][mb+g  ]);
                af[mt][3] = __float_as_uint(As[ks+q+4][mb+g+8]);
            }
            unsigned bf[4][2];
            #pragma unroll
            for (int nt=0; nt<4; nt++){
                int nb = wn*32 + nt*8;
                bf[nt][0] = __float_as_uint(Bs[ks+q  ][nb+g]);
                bf[nt][1] = __float_as_uint(Bs[ks+q+4][nb+g]);
            }
            #pragma unroll
            for (int mt=0; mt<4; mt++)
                #pragma unroll
                for (int nt=0; nt<4; nt++)
                    mma8(acc[mt][nt], af[mt], bf[nt]);
        }
    }
    // epilogue
    #pragma unroll
    for (int nt=0; nt<4; nt++) {
        int c = bn + wn*32 + nt*8 + q*2;
        float2 bv = make_float2(0.f, 0.f);
        if (bias) bv = *(const float2*)(bias + c);
        #pragma unroll
        for (int mt=0; mt<4; mt++) {
            int r0 = bm + wm*64 + mt*16 + g;
            if (r0 < M) {
                float2 o = make_float2(acc[mt][nt][0]+bv.x, acc[mt][nt][1]+bv.y);
                *(float2*)(C + (size_t)r0*ldc + c) = o;
            }
            if (r0 + 8 < M) {
                float2 o = make_float2(acc[mt][nt][2]+bv.x, acc[mt][nt][3]+bv.y);
                *(float2*)(C + (size_t)(r0+8)*ldc + c) = o;
            }
        }
    }
}

// ---------- wigner: msg = perm(wigner @ [x_src|x_dst]) * rad ----------------
__global__ void k_wigner(const float* __restrict__ x, const int* __restrict__ ei,
                         const float* __restrict__ wig, const float* __restrict__ rad,
                         float* __restrict__ sm)
{
    __shared__ float msg[25][128];
    __shared__ float wg[19][25];
    int e = blockIdx.x;
    int t = threadIdx.x; // 128
    int src = ei[e], dst = ei[NE + e];
    const float* xs = x + (size_t)src*1600;
    const float* xd = x + (size_t)dst*1600;
    int c = t & 63;
    if (t < 64) { for (int j=0;j<25;j++) msg[j][t] = xs[j*64+c]; }
    else        { for (int j=0;j<25;j++) msg[j][t] = xd[j*64+c]; }
    for (int i = t; i < 475; i += 128) {
        int p = i/25, j = i%25;
        wg[p][j] = wig[(size_t)e*475 + (size_t)c_PERM[p]*25 + j];
    }
    __syncthreads();
    const float* re = rad + (size_t)e*1536;
    float* so = sm + (size_t)e*2432;
    #pragma unroll
    for (int p = 0; p < 19; p++) {
        float acc = 0.f;
        #pragma unroll
        for (int j = 0; j < 25; j++) acc += wg[p][j]*msg[j][t];
        so[p*128 + t] = acc * re[c_RADOFF[p] + t];
    }
}

// ---------- grid stage: silu-gated S2 pointwise -----------------------------
__global__ void k_grid(const float* __restrict__ tmp0, const float* __restrict__ h1,
                       const float* __restrict__ tgrid, const float* __restrict__ fgrid,
                       float* __restrict__ h2)
{
    __shared__ float tg[100][20];
    __shared__ float fg[100][20];
    __shared__ float h[2][19][64];
    int t = threadIdx.x; // 128
    for (int i = t; i < 1900; i += 128) {
        int ba = i / 19, p = i % 19;
        tg[ba][p] = tgrid[ba*19 + c_PERM[p]];
        fg[ba][p] = fgrid[ba*19 + c_PERM[p]];
    }
    int el = t >> 6, c = t & 63;
    int e = blockIdx.x*2 + el;
    const float* t0 = tmp0 + (size_t)e*896;
    #pragma unroll
    for (int p = 0; p < 5; p++) h[el][p][c] = t0[576 + p*64 + c];
    const float* hh = h1 + (size_t)e*1216;
    #pragma unroll
    for (int p = 5; p < 19; p++) h[el][p][c] = hh[p*64 + c];
    __syncthreads();
    float s2[19];
    #pragma unroll
    for (int p=0;p<19;p++) s2[p]=0.f;
    for (int ba = 0; ba < 100; ba++) {
        float g = 0.f;
        #pragma unroll
        for (int p = 0; p < 19; p++) g += tg[ba][p]*h[el][p][c];
        g = siluf_(g);
        #pragma unroll
        for (int p = 0; p < 19; p++) s2[p] += fg[ba][p]*g;
    }
    float* o = h2 + (size_t)e*1216;
    o[c] = siluf_(t0[512 + c]);          // row 0 := silu(gate)
    #pragma unroll
    for (int p = 1; p < 19; p++) o[p*64 + c] = s2[p];
}

// ---------- alpha: LN + smooth-leaky-relu + dot, atomicMax ------------------
__global__ void k_alpha1(const float* __restrict__ tmp0, const int* __restrict__ ei,
                         const float* __restrict__ lng, const float* __restrict__ lnb,
                         const float* __restrict__ adot,
                         float* __restrict__ alpha, unsigned int* __restrict__ amax)
{
    int e = blockIdx.x;
    int w = threadIdx.x >> 5, lane = threadIdx.x & 31; // 8 warps = 8 heads
    const float* a = tmp0 + (size_t)e*896 + w*64;
    float v0 = a[lane], v1 = a[lane+32];
    float s = v0+v1;
    #pragma unroll
    for (int o=16;o;o>>=1) s += __shfl_xor_sync(0xffffffffu, s, o);
    float mu = s * (1.f/64.f);
    float d0=v0-mu, d1=v1-mu;
    float q = d0*d0+d1*d1;
    #pragma unroll
    for (int o=16;o;o>>=1) q += __shfl_xor_sync(0xffffffffu, q, o);
    float rstd = rsqrtf(q*(1.f/64.f) + 1e-5f);
    float x0 = slrelu_(d0*rstd*lng[lane]+lnb[lane]);
    float x1 = slrelu_(d1*rstd*lng[lane+32]+lnb[lane+32]);
    float p = x0*adot[w*64+lane] + x1*adot[w*64+lane+32];
    #pragma unroll
    for (int o=16;o;o>>=1) p += __shfl_xor_sync(0xffffffffu, p, o);
    if (lane == 0) {
        alpha[e*8+w] = p;
        int dst = ei[NE + e];
        unsigned int enc = __float_as_uint(p);
        enc = (enc & 0x80000000u) ? ~enc : (enc | 0x80000000u);
        atomicMax(&amax[dst*8+w], enc);
    }
}

__global__ void k_alpha2(float* __restrict__ alpha, const int* __restrict__ ei,
                         const unsigned int* __restrict__ amax, float* __restrict__ den)
{
    int i = blockIdx.x*256 + threadIdx.x;
    if (i >= NE*8) return;
    int e = i >> 3, h = i & 7;
    int dst = ei[NE + e];
    unsigned int u = amax[dst*8+h];
    float m = (u & 0x80000000u) ? __uint_as_float(u & 0x7FFFFFFFu) : __uint_as_float(~u);
    float ex = __expf(alpha[i] - m);
    alpha[i] = ex;
    atomicAdd(&den[dst*8+h], ex);
}

// ---------- attention weight + wigner_inv + segment-sum ---------------------
__global__ void k_attn(const float* __restrict__ h3, const float* __restrict__ winv,
                       const float* __restrict__ alpha, const float* __restrict__ den,
                       const int* __restrict__ ei, float* __restrict__ node)
{
    __shared__ float m[19][128];
    __shared__ float wi[25][20];
    __shared__ float wt[8];
    int e = blockIdx.x, t = threadIdx.x; // 128
    int dst = ei[NE + e];
    if (t < 8) wt[t] = alpha[e*8+t] / (den[dst*8+t] + 1e-16f);
    for (int i = t; i < 475; i += 128) {
        int r = i/19, p = i%19;
        wi[r][p] = winv[(size_t)e*475 + r*19 + c_PERM[p]];
    }
    __syncthreads();
    const float* hh = h3 + (size_t)e*2432;
    float w = wt[t >> 4];
    #pragma unroll
    for (int p = 0; p < 19; p++) m[p][t] = hh[p*128 + t] * w;
    __syncthreads();
    float* no = node + (size_t)dst*3200;
    #pragma unroll
    for (int r = 0; r < 25; r++) {
        float acc = 0.f;
        #pragma unroll
        for (int p = 0; p < 19; p++) acc += wi[r][p]*m[p][t];
        atomicAdd(&no[r*128 + t], acc);
    }
}

// ---------- output projection ----------------------------------------------
__global__ void k_proj(const float* __restrict__ node, const float* __restrict__ pw,
                       const float* __restrict__ pb, float* __restrict__ outp)
{
    __shared__ float wt[128*65];
    int bid = blockIdx.x;      // n*5 + l
    int n = bid / 5, l = bid % 5;
    int t = threadIdx.x;       // 64
    for (int i = t; i < 8192; i += 64) {
        int o = i >> 7, c = i & 127;
        wt[c*65 + o] = pw[l*8192 + i];
    }
    __syncthreads();
    int i0 = l*l, i1 = (l+1)*(l+1);
    for (int i = i0; i < i1; i++) {
        const float* nr = node + (size_t)n*3200 + i*128;
        float acc = (i == 0) ? pb[t] : 0.f;
        #pragma unroll 8
        for (int c = 0; c < 128; c++) acc += nr[c] * wt[c*65 + t];
        outp[(size_t)n*1600 + i*64 + t] = acc;
    }
}

// ----------------------------------------------------------------------------
extern "C" void kernel_launch(void* const* d_in, const int* in_sizes, int n_in,
                              void* d_out, int out_size)
{
    const float* x    = (const float*)d_in[0];
    const float* ed   = (const float*)d_in[1];
    const int*   ei   = (const int*)  d_in[2];
    const float* wig  = (const float*)d_in[3];
    const float* winv = (const float*)d_in[4];
    const float* tgr  = (const float*)d_in[5];
    const float* fgr  = (const float*)d_in[6];
    const float* rw1  = (const float*)d_in[7];
    const float* rb1  = (const float*)d_in[8];
    const float* rg1  = (const float*)d_in[9];
    const float* rbe1 = (const float*)d_in[10];
    const float* rw2  = (const float*)d_in[11];
    const float* rb2  = (const float*)d_in[12];
    const float* rg2  = (const float*)d_in[13];
    const float* rbe2 = (const float*)d_in[14];
    const float* rw3  = (const float*)d_in[15];
    const float* rb3  = (const float*)d_in[16];
    const float* c1w0 = (const float*)d_in[17];
    const float* c1b0 = (const float*)d_in[18];
    const float* c1w1 = (const float*)d_in[19];
    const float* c1w2 = (const float*)d_in[20];
    const float* c2w0 = (const float*)d_in[21];
    const float* c2b0 = (const float*)d_in[22];
    const float* c2w1 = (const float*)d_in[23];
    const float* c2w2 = (const float*)d_in[24];
    const float* alng = (const float*)d_in[25];
    const float* alnb = (const float*)d_in[26];
    const float* adot = (const float*)d_in[27];
    const float* pw   = (const float*)d_in[28];
    const float* pb   = (const float*)d_in[29];
    float* outp = (float*)d_out;

    void* p;
    cudaGetSymbolAddress(&p, g_hid);  float* hid  = (float*)p;
    cudaGetSymbolAddress(&p, g_rad);  float* rad  = (float*)p;
    cudaGetSymbolAddress(&p, g_sm);   float* sm   = (float*)p;
    cudaGetSymbolAddress(&p, g_tmp0); float* tmp0 = (float*)p;
    cudaGetSymbolAddress(&p, g_h1);   float* h1   = (float*)p;
    cudaGetSymbolAddress(&p, g_h2);   float* h2   = (float*)p;
    cudaGetSymbolAddress(&p, g_h3);   float* h3   = (float*)p;
    cudaGetSymbolAddress(&p, g_alf);  float* alf  = (float*)p;
    cudaGetSymbolAddress(&p, g_amax); unsigned int* amax = (unsigned int*)p;
    cudaGetSymbolAddress(&p, g_den);  float* den  = (float*)p;
    cudaGetSymbolAddress(&p, g_node); float* node = (float*)p;
    cudaGetSymbolAddress(&p, g_wp);   float* wp   = (float*)p;

    const int MB = (NE + 127) / 128;   // 157

    k_init<<<(NN*3200 + 255)/256, 256>>>(node, amax, den);

    // weight prep (tf32 round; complex weights expanded to real form)
    k_cvtw<<<(98304+255)/256, 256>>>(rw3,  wp + WP_RAD,  98304);
    k_cvtw<<<(573440+255)/256, 256>>>(c1w0, wp + WP_C1G0, 573440);
    k_cvtw<<<(204800+255)/256, 256>>>(c2w0, wp + WP_C2G0, 204800);
    k_prepw<<<(256*512+255)/256, 256>>>(c1w1, wp + WP_C1M1, 256, 512);
    k_prepw<<<(192*384+255)/256, 256>>>(c1w2, wp + WP_C1M2, 192, 384);
    k_prepw<<<(512*256+255)/256, 256>>>(c2w1, wp + WP_C2M1, 512, 256);
    k_prepw<<<(384*192+255)/256, 256>>>(c2w2, wp + WP_C2M2, 384, 192);

    k_radial<<<512, 64>>>(ed, rw1, rb1, rg1, rbe1, rw2, rb2, rg2, rbe2, hid);
    k_gemm_t<<<dim3(MB, 12), 256>>>(hid, 64, wp + WP_RAD, rb3, rad, 1536, NE, 1536, 64);
    k_wigner<<<NE, 128>>>(x, ei, wig, rad, sm);
    // conv1
    k_gemm_t<<<dim3(MB, 7), 256>>>(sm, 2432, wp + WP_C1G0, c1b0, tmp0, 896, NE, 896, 640);
    k_gemm_t<<<dim3(MB, 4), 256>>>(sm+640,  2432, wp + WP_C1M1, nullptr, h1+320, 1216, NE, 512, 1024);
    k_gemm_t<<<dim3(MB, 3), 256>>>(sm+1664, 2432, wp + WP_C1M2, nullptr, h1+832, 1216, NE, 384, 768);
    // grid nonlinearity
    k_grid<<<NE/2, 128>>>(tmp0, h1, tgr, fgr, h2);
    // conv2
    k_gemm_t<<<dim3(MB, 5), 256>>>(h2, 1216, wp + WP_C2G0, c2b0, h3, 2432, NE, 640, 320);
    k_gemm_t<<<dim3(MB, 8), 256>>>(h2+320, 1216, wp + WP_C2M1, nullptr, h3+640,  2432, NE, 1024, 512);
    k_gemm_t<<<dim3(MB, 6), 256>>>(h2+832, 1216, wp + WP_C2M2, nullptr, h3+1664, 2432, NE, 768, 384);
    // attention
    k_alpha1<<<NE, 256>>>(tmp0, ei, alng, alnb, adot, alf, amax);
    k_alpha2<<<(NE*8 + 255)/256, 256>>>(alf, ei, amax, den);
    k_attn<<<NE, 128>>>(h3, winv, alf, den, ei, node);
    // projection
    k_proj<<<NN*5, 64>>>(node, pw, pb, outp);
}

// round 5
// speedup vs baseline: 1.6538x; 1.0074x over previous
#include <cuda_runtime.h>
#include <cuda_bf16.h>

#define NE 20000
#define NN 1000

// permuted row order: m=0 rows(5), +1(4), -1(4), +2(3), -2(3)
__constant__ int c_PERM[19]   = {0,2,6,11,16, 3,7,12,17, 1,5,10,15, 8,13,18, 4,9,14};
__constant__ int c_RADOFF[19] = {0,128,256,384,512, 640,768,896,1024, 640,768,896,1024,
                                 1152,1280,1408, 1152,1280,1408};

// ----------------- scratch (__device__ globals; no runtime alloc) -----------
__device__ __align__(16) float g_hid [(size_t)NE*64];
__device__ __align__(16) float g_rad [(size_t)NE*1536];
__device__ __align__(16) float g_sm  [(size_t)NE*2432];   // wigner out, permuted, rad-scaled
__device__ __align__(16) float g_tmp0[(size_t)NE*896];    // conv1 gemm0 out (alpha|gate|m0)
__device__ __align__(16) float g_h1  [(size_t)NE*1216];   // conv1 out rows 5..18 (64/row)
__device__ __align__(16) float g_h2  [(size_t)NE*1216];   // grid-stage out (19x64 permuted)
__device__ __align__(16) float g_h3  [(size_t)NE*2432];   // conv2 out (19x128 permuted)
__device__ __align__(16) float g_alf [(size_t)NE*8];
__device__ unsigned int        g_amax[NN*8];
__device__ float               g_den [NN*8];
__device__ __align__(16) float g_node[(size_t)NN*3200];
// tf32-prepped weights (plain + complex-expanded), constexpr offsets below
__device__ __align__(16) float g_wp  [2514944];

// offsets into g_wp
#define WP_RAD   0
#define WP_C1G0  98304
#define WP_C1M1  671744
#define WP_C1M2  1196032
#define WP_C2G0  1490944
#define WP_C2M1  1695744
#define WP_C2M2  2220032

// ----------------- helpers --------------------------------------------------
__device__ __forceinline__ float sigmoidf_(float x){ return 1.f/(1.f+__expf(-x)); }
__device__ __forceinline__ float siluf_(float x){ return x*sigmoidf_(x); }
__device__ __forceinline__ float slrelu_(float x){ return 0.6f*x + 0.4f*x*(2.f*sigmoidf_(x)-1.f); }

__device__ __forceinline__ float tf32f_(float x){
    unsigned r; asm("cvt.rna.tf32.f32 %0, %1;" : "=r"(r) : "f"(x));
    return __uint_as_float(r);
}

// m16n8k8 tf32 mma, fp32 accumulate
__device__ __forceinline__ void mma8(float* d, const unsigned* a, const unsigned* b){
    asm("mma.sync.aligned.m16n8k8.row.col.f32.tf32.tf32.f32 "
        "{%0,%1,%2,%3}, {%4,%5,%6,%7}, {%8,%9}, {%0,%1,%2,%3};"
        : "+f"(d[0]), "+f"(d[1]), "+f"(d[2]), "+f"(d[3])
        : "r"(a[0]), "r"(a[1]), "r"(a[2]), "r"(a[3]), "r"(b[0]), "r"(b[1]));
}

// reduce over 64 threads (2 warps), blockDim==64
__device__ __forceinline__ float red64(float v, float* sbuf, int t){
    #pragma unroll
    for (int o=16;o;o>>=1) v += __shfl_xor_sync(0xffffffffu, v, o);
    if ((t&31)==0) sbuf[t>>5] = v;
    __syncthreads();
    float r = sbuf[0]+sbuf[1];
    __syncthreads();
    return r;
}

// ----------------- init -----------------------------------------------------
__global__ void k_init(float* node, unsigned int* amax, float* den){
    int i = blockIdx.x*256 + threadIdx.x;
    if (i < NN*3200) node[i] = 0.f;
    if (i < NN*8) { amax[i] = 0u; den[i] = 0.f; }
}

// ----------------- weight prep ----------------------------------------------
__global__ void k_cvtw(const float* __restrict__ w, float* __restrict__ o, int n){
    int i = blockIdx.x*256 + threadIdx.x;
    if (i < n) o[i] = tf32f_(w[i]);
}
// complex: w[(2N)xK] (rows 0..N-1 = Wr, N..2N-1 = Wi) ->
// wp[(2N)x(2K)]: row n = [Wr[n] | -Wi[n]], row N+n = [Wi[n] | Wr[n]]
__global__ void k_prepw(const float* __restrict__ w, float* __restrict__ wp, int N, int K){
    int i = blockIdx.x*256 + threadIdx.x;
    if (i >= N*K) return;
    int n = i / K, k = i % K;
    float wr = tf32f_(w[(size_t)n*K + k]);
    float wi = tf32f_(w[(size_t)(N+n)*K + k]);
    size_t row0 = (size_t)n*2*K, row1 = (size_t)(N+n)*2*K;
    wp[row0 + k]     = wr;
    wp[row0 + K + k] = -wi;
    wp[row1 + k]     = wi;
    wp[row1 + K + k] = wr;
}

// ----------------- radial layers 1+2 (LN + silu) ----------------------------
__global__ void k_radial(const float* __restrict__ ed,
                         const float* __restrict__ w1, const float* __restrict__ b1,
                         const float* __restrict__ g1, const float* __restrict__ be1,
                         const float* __restrict__ w2, const float* __restrict__ b2,
                         const float* __restrict__ g2, const float* __restrict__ be2,
                         float* __restrict__ outp)
{
    __shared__ float w1t[64*64], w2t[64*64];
    __shared__ float xin[64], hmid[64];
    __shared__ float sbuf[2];
    int t = threadIdx.x; // 64
    for (int i = t; i < 4096; i += 64) {
        int r = i >> 6, c = i & 63;
        w1t[c*64 + r] = w1[i];
        w2t[c*64 + r] = w2[i];
    }
    __syncthreads();
    for (int e = blockIdx.x; e < NE; e += gridDim.x) {
        xin[t] = ed[(size_t)e*64 + t];
        __syncthreads();
        float acc = b1[t];
        #pragma unroll 8
        for (int k = 0; k < 64; k++) acc += xin[k]*w1t[k*64+t];
        float mu = red64(acc, sbuf, t) * (1.f/64.f);
        float d = acc - mu;
        float var = red64(d*d, sbuf, t) * (1.f/64.f);
        float v = d*rsqrtf(var+1e-5f)*g1[t] + be1[t];
        hmid[t] = siluf_(v);
        __syncthreads();
        acc = b2[t];
        #pragma unroll 8
        for (int k = 0; k < 64; k++) acc += hmid[k]*w2t[k*64+t];
        mu = red64(acc, sbuf, t) * (1.f/64.f);
        d = acc - mu;
        var = red64(d*d, sbuf, t) * (1.f/64.f);
        v = d*rsqrtf(var+1e-5f)*g2[t] + be2[t];
        outp[(size_t)e*64 + t] = siluf_(v);
        __syncthreads();
    }
}

// ========== tf32 tensor-core GEMM: C[M,N] = A[M,K] @ W[N,K]^T (+bias) =======
// block tile 128x128, 8 warps (2x4), warp tile m64n32, BK=16.
// Double-buffered smem with register prefetch of the next k-tile.
// Requires: N % 128 == 0, K % 16 == 0. W already tf32-rounded. A rounded here.
__global__ void __launch_bounds__(256, 2) k_gemm_t(
        const float* __restrict__ A, int lda,
        const float* __restrict__ W,
        const float* __restrict__ bias,
        float* __restrict__ C, int ldc, int M, int N, int K)
{
    __shared__ float As[2][16][136];
    __shared__ float Bs[2][16][136];
    const int tid = threadIdx.x;
    const int bm = blockIdx.x*128, bn = blockIdx.y*128;
    const int wid = tid >> 5, lane = tid & 31;
    const int wm = wid & 1, wn = wid >> 1;        // 2 x 4 warps
    const int g = lane >> 2, q = lane & 3;
    const int srow = tid & 127, sq = tid >> 7;    // staging: row, k-half
    float acc[4][4][4];
    #pragma unroll
    for (int i=0;i<4;i++)
        #pragma unroll
        for (int j=0;j<4;j++)
            #pragma unroll
            for (int r=0;r<4;r++) acc[i][j][r] = 0.f;
    const bool aval = (bm + srow) < M;
    const float* Ap = A + (size_t)(bm+srow)*lda + sq*8;
    const float* Wp = W + (size_t)(bn+srow)*K + sq*8;

    // prologue: load + store stage 0
    {
        float4 a0 = make_float4(0.f,0.f,0.f,0.f), a1 = a0;
        if (aval) { a0 = *(const float4*)(Ap); a1 = *(const float4*)(Ap + 4); }
        float4 w0 = *(const float4*)(Wp);
        float4 w1 = *(const float4*)(Wp + 4);
        As[0][sq*8+0][srow]=tf32f_(a0.x); As[0][sq*8+1][srow]=tf32f_(a0.y);
        As[0][sq*8+2][srow]=tf32f_(a0.z); As[0][sq*8+3][srow]=tf32f_(a0.w);
        As[0][sq*8+4][srow]=tf32f_(a1.x); As[0][sq*8+5][srow]=tf32f_(a1.y);
        As[0][sq*8+6][srow]=tf32f_(a1.z); As[0][sq*8+7][srow]=tf32f_(a1.w);
        Bs[0][sq*8+0][srow]=w0.x; Bs[0][sq*8+1][srow]=w0.y;
        Bs[0][sq*8+2][srow]=w0.z; Bs[0][sq*8+3][srow]=w0.w;
        Bs[0][sq*8+4][srow]=w1.x; Bs[0][sq*8+5][srow]=w1.y;
        Bs[0][sq*8+6][srow]=w1.z; Bs[0][sq*8+7][srow]=w1.w;
    }
    __syncthreads();

    const int nit = K >> 4;
    int buf = 0;
    for (int it = 0; it < nit; it++) {
        // prefetch next k-tile into registers (latency hidden under MMA)
        float4 na0 = make_float4(0.f,0.f,0.f,0.f), na1 = na0, nw0 = na0, nw1 = na0;
        const bool more = (it + 1 < nit);
        if (more) {
            int k0 = (it + 1) << 4;
            if (aval) { na0 = *(const float4*)(Ap + k0); na1 = *(const float4*)(Ap + k0 + 4); }
            nw0 = *(const float4*)(Wp + k0);
            nw1 = *(const float4*)(Wp + k0 + 4);
        }
        // MMA on current stage
        #pragma unroll
        for (int ks = 0; ks < 16; ks += 8) {
            unsigned af[4][4];
            #pragma unroll
            for (int mt=0; mt<4; mt++){
                int mb = wm*64 + mt*16;
                af[mt][0] = __float_as_uint(As[buf][ks+q  ][mb+g  ]);
                af[mt][1] = __float_as_uint(As[buf][ks+q  ][mb+g+8]);
                af[mt][2] = __float_as_uint(As[buf][ks+q+4][mb+g  ]);
                af[mt][3] = __float_as_uint(As[buf][ks+q+4][mb+g+8]);
            }
            unsigned bf[4][2];
            #pragma unroll
            for (int nt=0; nt<4; nt++){
                int nb = wn*32 + nt*8;
                bf[nt][0] = __float_as_uint(Bs[buf][ks+q  ][nb+g]);
                bf[nt][1] = __float_as_uint(Bs[buf][ks+q+4][nb+g]);
            }
            #pragma unroll
            for (int mt=0; mt<4; mt++)
                #pragma unroll
                for (int nt=0; nt<4; nt++)
                    mma8(acc[mt][nt], af[mt], bf[nt]);
        }
        if (more) {
            int nb = buf ^ 1;
            As[nb][sq*8+0][srow]=tf32f_(na0.x); As[nb][sq*8+1][srow]=tf32f_(na0.y);
            As[nb][sq*8+2][srow]=tf32f_(na0.z); As[nb][sq*8+3][srow]=tf32f_(na0.w);
            As[nb][sq*8+4][srow]=tf32f_(na1.x); As[nb][sq*8+5][srow]=tf32f_(na1.y);
            As[nb][sq*8+6][srow]=tf32f_(na1.z); As[nb][sq*8+7][srow]=tf32f_(na1.w);
            Bs[nb][sq*8+0][srow]=nw0.x; Bs[nb][sq*8+1][srow]=nw0.y;
            Bs[nb][sq*8+2][srow]=nw0.z; Bs[nb][sq*8+3][srow]=nw0.w;
            Bs[nb][sq*8+4][srow]=nw1.x; Bs[nb][sq*8+5][srow]=nw1.y;
            Bs[nb][sq*8+6][srow]=nw1.z; Bs[nb][sq*8+7][srow]=nw1.w;
            __syncthreads();
            buf = nb;
        }
    }
    // epilogue
    #pragma unroll
    for (int nt=0; nt<4; nt++) {
        int c = bn + wn*32 + nt*8 + q*2;
        float2 bv = make_float2(0.f, 0.f);
        if (bias) bv = *(const float2*)(bias + c);
        #pragma unroll
        for (int mt=0; mt<4; mt++) {
            int r0 = bm + wm*64 + mt*16 + g;
            if (r0 < M) {
                float2 o = make_float2(acc[mt][nt][0]+bv.x, acc[mt][nt][1]+bv.y);
                *(float2*)(C + (size_t)r0*ldc + c) = o;
            }
            if (r0 + 8 < M) {
                float2 o = make_float2(acc[mt][nt][2]+bv.x, acc[mt][nt][3]+bv.y);
                *(float2*)(C + (size_t)(r0+8)*ldc + c) = o;
            }
        }
    }
}

// ---------- wigner: msg = perm(wigner @ [x_src|x_dst]) * rad ----------------
__global__ void k_wigner(const float* __restrict__ x, const int* __restrict__ ei,
                         const float* __restrict__ wig, const float* __restrict__ rad,
                         float* __restrict__ sm)
{
    __shared__ float msg[25][128];
    __shared__ float wg[19][25];
    int e = blockIdx.x;
    int t = threadIdx.x; // 128
    int src = ei[e], dst = ei[NE + e];
    const float* xs = x + (size_t)src*1600;
    const float* xd = x + (size_t)dst*1600;
    int c = t & 63;
    if (t < 64) { for (int j=0;j<25;j++) msg[j][t] = xs[j*64+c]; }
    else        { for (int j=0;j<25;j++) msg[j][t] = xd[j*64+c]; }
    for (int i = t; i < 475; i += 128) {
        int p = i/25, j = i%25;
        wg[p][j] = wig[(size_t)e*475 + (size_t)c_PERM[p]*25 + j];
    }
    __syncthreads();
    const float* re = rad + (size_t)e*1536;
    float* so = sm + (size_t)e*2432;
    #pragma unroll
    for (int p = 0; p < 19; p++) {
        float acc = 0.f;
        #pragma unroll
        for (int j = 0; j < 25; j++) acc += wg[p][j]*msg[j][t];
        so[p*128 + t] = acc * re[c_RADOFF[p] + t];
    }
}

// ---------- grid stage: silu-gated S2 pointwise -----------------------------
__global__ void k_grid(const float* __restrict__ tmp0, const float* __restrict__ h1,
                       const float* __restrict__ tgrid, const float* __restrict__ fgrid,
                       float* __restrict__ h2)
{
    __shared__ float tg[100][20];
    __shared__ float fg[100][20];
    __shared__ float h[2][19][64];
    int t = threadIdx.x; // 128
    for (int i = t; i < 1900; i += 128) {
        int ba = i / 19, p = i % 19;
        tg[ba][p] = tgrid[ba*19 + c_PERM[p]];
        fg[ba][p] = fgrid[ba*19 + c_PERM[p]];
    }
    int el = t >> 6, c = t & 63;
    int e = blockIdx.x*2 + el;
    const float* t0 = tmp0 + (size_t)e*896;
    #pragma unroll
    for (int p = 0; p < 5; p++) h[el][p][c] = t0[576 + p*64 + c];
    const float* hh = h1 + (size_t)e*1216;
    #pragma unroll
    for (int p = 5; p < 19; p++) h[el][p][c] = hh[p*64 + c];
    __syncthreads();
    float s2[19];
    #pragma unroll
    for (int p=0;p<19;p++) s2[p]=0.f;
    for (int ba = 0; ba < 100; ba++) {
        float g = 0.f;
        #pragma unroll
        for (int p = 0; p < 19; p++) g += tg[ba][p]*h[el][p][c];
        g = siluf_(g);
        #pragma unroll
        for (int p = 0; p < 19; p++) s2[p] += fg[ba][p]*g;
    }
    float* o = h2 + (size_t)e*1216;
    o[c] = siluf_(t0[512 + c]);          // row 0 := silu(gate)
    #pragma unroll
    for (int p = 1; p < 19; p++) o[p*64 + c] = s2[p];
}

// ---------- alpha: LN + smooth-leaky-relu + dot, atomicMax ------------------
__global__ void k_alpha1(const float* __restrict__ tmp0, const int* __restrict__ ei,
                         const float* __restrict__ lng, const float* __restrict__ lnb,
                         const float* __restrict__ adot,
                         float* __restrict__ alpha, unsigned int* __restrict__ amax)
{
    int e = blockIdx.x;
    int w = threadIdx.x >> 5, lane = threadIdx.x & 31; // 8 warps = 8 heads
    const float* a = tmp0 + (size_t)e*896 + w*64;
    float v0 = a[lane], v1 = a[lane+32];
    float s = v0+v1;
    #pragma unroll
    for (int o=16;o;o>>=1) s += __shfl_xor_sync(0xffffffffu, s, o);
    float mu = s * (1.f/64.f);
    float d0=v0-mu, d1=v1-mu;
    float q = d0*d0+d1*d1;
    #pragma unroll
    for (int o=16;o;o>>=1) q += __shfl_xor_sync(0xffffffffu, q, o);
    float rstd = rsqrtf(q*(1.f/64.f) + 1e-5f);
    float x0 = slrelu_(d0*rstd*lng[lane]+lnb[lane]);
    float x1 = slrelu_(d1*rstd*lng[lane+32]+lnb[lane+32]);
    float p = x0*adot[w*64+lane] + x1*adot[w*64+lane+32];
    #pragma unroll
    for (int o=16;o;o>>=1) p += __shfl_xor_sync(0xffffffffu, p, o);
    if (lane == 0) {
        alpha[e*8+w] = p;
        int dst = ei[NE + e];
        unsigned int enc = __float_as_uint(p);
        enc = (enc & 0x80000000u) ? ~enc : (enc | 0x80000000u);
        atomicMax(&amax[dst*8+w], enc);
    }
}

__global__ void k_alpha2(float* __restrict__ alpha, const int* __restrict__ ei,
                         const unsigned int* __restrict__ amax, float* __restrict__ den)
{
    int i = blockIdx.x*256 + threadIdx.x;
    if (i >= NE*8) return;
    int e = i >> 3, h = i & 7;
    int dst = ei[NE + e];
    unsigned int u = amax[dst*8+h];
    float m = (u & 0x80000000u) ? __uint_as_float(u & 0x7FFFFFFFu) : __uint_as_float(~u);
    float ex = __expf(alpha[i] - m);
    alpha[i] = ex;
    atomicAdd(&den[dst*8+h], ex);
}

// ---------- attention weight + wigner_inv + segment-sum ---------------------
__global__ void k_attn(const float* __restrict__ h3, const float* __restrict__ winv,
                       const float* __restrict__ alpha, const float* __restrict__ den,
                       const int* __restrict__ ei, float* __restrict__ node)
{
    __shared__ float m[19][128];
    __shared__ float wi[25][20];
    __shared__ float wt[8];
    int e = blockIdx.x, t = threadIdx.x; // 128
    int dst = ei[NE + e];
    if (t < 8) wt[t] = alpha[e*8+t] / (den[dst*8+t] + 1e-16f);
    for (int i = t; i < 475; i += 128) {
        int r = i/19, p = i%19;
        wi[r][p] = winv[(size_t)e*475 + r*19 + c_PERM[p]];
    }
    __syncthreads();
    const float* hh = h3 + (size_t)e*2432;
    float w = wt[t >> 4];
    #pragma unroll
    for (int p = 0; p < 19; p++) m[p][t] = hh[p*128 + t] * w;
    __syncthreads();
    float* no = node + (size_t)dst*3200;
    #pragma unroll
    for (int r = 0; r < 25; r++) {
        float acc = 0.f;
        #pragma unroll
        for (int p = 0; p < 19; p++) acc += wi[r][p]*m[p][t];
        atomicAdd(&no[r*128 + t], acc);
    }
}

// ---------- output projection ----------------------------------------------
__global__ void k_proj(const float* __restrict__ node, const float* __restrict__ pw,
                       const float* __restrict__ pb, float* __restrict__ outp)
{
    __shared__ float wt[128*65];
    int bid = blockIdx.x;      // n*5 + l
    int n = bid / 5, l = bid % 5;
    int t = threadIdx.x;       // 64
    for (int i = t; i < 8192; i += 64) {
        int o = i >> 7, c = i & 127;
        wt[c*65 + o] = pw[l*8192 + i];
    }
    __syncthreads();
    int i0 = l*l, i1 = (l+1)*(l+1);
    for (int i = i0; i < i1; i++) {
        const float* nr = node + (size_t)n*3200 + i*128;
        float acc = (i == 0) ? pb[t] : 0.f;
        #pragma unroll 8
        for (int c = 0; c < 128; c++) acc += nr[c] * wt[c*65 + t];
        outp[(size_t)n*1600 + i*64 + t] = acc;
    }
}

// ----------------------------------------------------------------------------
extern "C" void kernel_launch(void* const* d_in, const int* in_sizes, int n_in,
                              void* d_out, int out_size)
{
    const float* x    = (const float*)d_in[0];
    const float* ed   = (const float*)d_in[1];
    const int*   ei   = (const int*)  d_in[2];
    const float* wig  = (const float*)d_in[3];
    const float* winv = (const float*)d_in[4];
    const float* tgr  = (const float*)d_in[5];
    const float* fgr  = (const float*)d_in[6];
    const float* rw1  = (const float*)d_in[7];
    const float* rb1  = (const float*)d_in[8];
    const float* rg1  = (const float*)d_in[9];
    const float* rbe1 = (const float*)d_in[10];
    const float* rw2  = (const float*)d_in[11];
    const float* rb2  = (const float*)d_in[12];
    const float* rg2  = (const float*)d_in[13];
    const float* rbe2 = (const float*)d_in[14];
    const float* rw3  = (const float*)d_in[15];
    const float* rb3  = (const float*)d_in[16];
    const float* c1w0 = (const float*)d_in[17];
    const float* c1b0 = (const float*)d_in[18];
    const float* c1w1 = (const float*)d_in[19];
    const float* c1w2 = (const float*)d_in[20];
    const float* c2w0 = (const float*)d_in[21];
    const float* c2b0 = (const float*)d_in[22];
    const float* c2w1 = (const float*)d_in[23];
    const float* c2w2 = (const float*)d_in[24];
    const float* alng = (const float*)d_in[25];
    const float* alnb = (const float*)d_in[26];
    const float* adot = (const float*)d_in[27];
    const float* pw   = (const float*)d_in[28];
    const float* pb   = (const float*)d_in[29];
    float* outp = (float*)d_out;

    void* p;
    cudaGetSymbolAddress(&p, g_hid);  float* hid  = (float*)p;
    cudaGetSymbolAddress(&p, g_rad);  float* rad  = (float*)p;
    cudaGetSymbolAddress(&p, g_sm);   float* sm   = (float*)p;
    cudaGetSymbolAddress(&p, g_tmp0); float* tmp0 = (float*)p;
    cudaGetSymbolAddress(&p, g_h1);   float* h1   = (float*)p;
    cudaGetSymbolAddress(&p, g_h2);   float* h2   = (float*)p;
    cudaGetSymbolAddress(&p, g_h3);   float* h3   = (float*)p;
    cudaGetSymbolAddress(&p, g_alf);  float* alf  = (float*)p;
    cudaGetSymbolAddress(&p, g_amax); unsigned int* amax = (unsigned int*)p;
    cudaGetSymbolAddress(&p, g_den);  float* den  = (float*)p;
    cudaGetSymbolAddress(&p, g_node); float* node = (float*)p;
    cudaGetSymbolAddress(&p, g_wp);   float* wp   = (float*)p;

    const int MB = (NE + 127) / 128;   // 157

    k_init<<<(NN*3200 + 255)/256, 256>>>(node, amax, den);

    // weight prep (tf32 round; complex weights expanded to real form)
    k_cvtw<<<(98304+255)/256, 256>>>(rw3,  wp + WP_RAD,  98304);
    k_cvtw<<<(573440+255)/256, 256>>>(c1w0, wp + WP_C1G0, 573440);
    k_cvtw<<<(204800+255)/256, 256>>>(c2w0, wp + WP_C2G0, 204800);
    k_prepw<<<(256*512+255)/256, 256>>>(c1w1, wp + WP_C1M1, 256, 512);
    k_prepw<<<(192*384+255)/256, 256>>>(c1w2, wp + WP_C1M2, 192, 384);
    k_prepw<<<(512*256+255)/256, 256>>>(c2w1, wp + WP_C2M1, 512, 256);
    k_prepw<<<(384*192+255)/256, 256>>>(c2w2, wp + WP_C2M2, 384, 192);

    k_radial<<<512, 64>>>(ed, rw1, rb1, rg1, rbe1, rw2, rb2, rg2, rbe2, hid);
    k_gemm_t<<<dim3(MB, 12), 256>>>(hid, 64, wp + WP_RAD, rb3, rad, 1536, NE, 1536, 64);
    k_wigner<<<NE, 128>>>(x, ei, wig, rad, sm);
    // conv1
    k_gemm_t<<<dim3(MB, 7), 256>>>(sm, 2432, wp + WP_C1G0, c1b0, tmp0, 896, NE, 896, 640);
    k_gemm_t<<<dim3(MB, 4), 256>>>(sm+640,  2432, wp + WP_C1M1, nullptr, h1+320, 1216, NE, 512, 1024);
    k_gemm_t<<<dim3(MB, 3), 256>>>(sm+1664, 2432, wp + WP_C1M2, nullptr, h1+832, 1216, NE, 384, 768);
    // grid nonlinearity
    k_grid<<<NE/2, 128>>>(tmp0, h1, tgr, fgr, h2);
    // conv2
    k_gemm_t<<<dim3(MB, 5), 256>>>(h2, 1216, wp + WP_C2G0, c2b0, h3, 2432, NE, 640, 320);
    k_gemm_t<<<dim3(MB, 8), 256>>>(h2+320, 1216, wp + WP_C2M1, nullptr, h3+640,  2432, NE, 1024, 512);
    k_gemm_t<<<dim3(MB, 6), 256>>>(h2+832, 1216, wp + WP_C2M2, nullptr, h3+1664, 2432, NE, 768, 384);
    // attention
    k_alpha1<<<NE, 256>>>(tmp0, ei, alng, alnb, adot, alf, amax);
    k_alpha2<<<(NE*8 + 255)/256, 256>>>(alf, ei, amax, den);
    k_attn<<<NE, 128>>>(h3, winv, alf, den, ei, node);
    // projection
    k_proj<<<NN*5, 64>>>(node, pw, pb, outp);
}

// round 8
// speedup vs baseline: 1.8260x; 1.1041x over previous
#include <cuda_runtime.h>
#include <cuda_bf16.h>
#include <cstdint>

#define NE 20000
#define NN 1000

// permuted row order: m=0 rows(5), +1(4), -1(4), +2(3), -2(3)
__constant__ int c_PERM[19]   = {0,2,6,11,16, 3,7,12,17, 1,5,10,15, 8,13,18, 4,9,14};
__constant__ int c_RADOFF[19] = {0,128,256,384,512, 640,768,896,1024, 640,768,896,1024,
                                 1152,1280,1408, 1152,1280,1408};

// ----------------- scratch (__device__ globals; no runtime alloc) -----------
__device__ __align__(16) float g_hid [(size_t)NE*64];
__device__ __align__(16) float g_rad [(size_t)NE*1536];
__device__ __align__(16) float g_sm  [(size_t)NE*2432];   // wigner out, permuted, rad-scaled
__device__ __align__(16) float g_tmp0[(size_t)NE*896];    // conv1 gemm0 out (alpha|gate|m0)
__device__ __align__(16) float g_h1  [(size_t)NE*1216];   // conv1 out rows 5..18 (64/row)
__device__ __align__(16) float g_h2  [(size_t)NE*1216];   // grid-stage out (19x64 permuted)
__device__ __align__(16) float g_h3  [(size_t)NE*2432];   // conv2 out (19x128 permuted)
__device__ __align__(16) float g_alf [(size_t)NE*8];
__device__ unsigned int        g_amax[NN*8];
__device__ float               g_den [NN*8];
__device__ __align__(16) float g_node[(size_t)NN*3200];
// tf32-prepped weights (plain + complex-expanded), constexpr offsets below
__device__ __align__(16) float g_wp  [2514944];

// offsets into g_wp
#define WP_RAD   0
#define WP_C1G0  98304
#define WP_C1M1  671744
#define WP_C1M2  1196032
#define WP_C2G0  1490944
#define WP_C2M1  1695744
#define WP_C2M2  2220032

// ----------------- helpers --------------------------------------------------
__device__ __forceinline__ float sigmoidf_(float x){ return 1.f/(1.f+__expf(-x)); }
__device__ __forceinline__ float siluf_(float x){ return x*sigmoidf_(x); }
__device__ __forceinline__ float slrelu_(float x){ return 0.6f*x + 0.4f*x*(2.f*sigmoidf_(x)-1.f); }

__device__ __forceinline__ float tf32f_(float x){
    unsigned r; asm("cvt.rna.tf32.f32 %0, %1;" : "=r"(r) : "f"(x));
    return __uint_as_float(r);
}

// m16n8k8 tf32 mma, fp32 accumulate
__device__ __forceinline__ void mma8(float* d, const unsigned* a, const unsigned* b){
    asm("mma.sync.aligned.m16n8k8.row.col.f32.tf32.tf32.f32 "
        "{%0,%1,%2,%3}, {%4,%5,%6,%7}, {%8,%9}, {%0,%1,%2,%3};"
        : "+f"(d[0]), "+f"(d[1]), "+f"(d[2]), "+f"(d[3])
        : "r"(a[0]), "r"(a[1]), "r"(a[2]), "r"(a[3]), "r"(b[0]), "r"(b[1]));
}

// reduce over 64 threads (2 warps), blockDim==64
__device__ __forceinline__ float red64(float v, float* sbuf, int t){
    #pragma unroll
    for (int o=16;o;o>>=1) v += __shfl_xor_sync(0xffffffffu, v, o);
    if ((t&31)==0) sbuf[t>>5] = v;
    __syncthreads();
    float r = sbuf[0]+sbuf[1];
    __syncthreads();
    return r;
}

// ----------------- init -----------------------------------------------------
__global__ void k_init(float* node, unsigned int* amax, float* den){
    int i = blockIdx.x*256 + threadIdx.x;
    if (i < NN*3200) node[i] = 0.f;
    if (i < NN*8) { amax[i] = 0u; den[i] = 0.f; }
}

// ----------------- weight prep ----------------------------------------------
__global__ void k_cvtw(const float* __restrict__ w, float* __restrict__ o, int n){
    int i = blockIdx.x*256 + threadIdx.x;
    if (i < n) o[i] = tf32f_(w[i]);
}
// complex: w[(2N)xK] (rows 0..N-1 = Wr, N..2N-1 = Wi) ->
// wp[(2N)x(2K)]: row n = [Wr[n] | -Wi[n]], row N+n = [Wi[n] | Wr[n]]
__global__ void k_prepw(const float* __restrict__ w, float* __restrict__ wp, int N, int K){
    int i = blockIdx.x*256 + threadIdx.x;
    if (i >= N*K) return;
    int n = i / K, k = i % K;
    float wr = tf32f_(w[(size_t)n*K + k]);
    float wi = tf32f_(w[(size_t)(N+n)*K + k]);
    size_t row0 = (size_t)n*2*K, row1 = (size_t)(N+n)*2*K;
    wp[row0 + k]     = wr;
    wp[row0 + K + k] = -wi;
    wp[row1 + k]     = wi;
    wp[row1 + K + k] = wr;
}

// ----------------- radial layers 1+2 (LN + silu) ----------------------------
__global__ void k_radial(const float* __restrict__ ed,
                         const float* __restrict__ w1, const float* __restrict__ b1,
                         const float* __restrict__ g1, const float* __restrict__ be1,
                         const float* __restrict__ w2, const float* __restrict__ b2,
                         const float* __restrict__ g2, const float* __restrict__ be2,
                         float* __restrict__ outp)
{
    __shared__ float w1t[64*64], w2t[64*64];
    __shared__ float xin[64], hmid[64];
    __shared__ float sbuf[2];
    int t = threadIdx.x; // 64
    for (int i = t; i < 4096; i += 64) {
        int r = i >> 6, c = i & 63;
        w1t[c*64 + r] = w1[i];
        w2t[c*64 + r] = w2[i];
    }
    __syncthreads();
    for (int e = blockIdx.x; e < NE; e += gridDim.x) {
        xin[t] = ed[(size_t)e*64 + t];
        __syncthreads();
        float acc = b1[t];
        #pragma unroll 8
        for (int k = 0; k < 64; k++) acc += xin[k]*w1t[k*64+t];
        float mu = red64(acc, sbuf, t) * (1.f/64.f);
        float d = acc - mu;
        float var = red64(d*d, sbuf, t) * (1.f/64.f);
        float v = d*rsqrtf(var+1e-5f)*g1[t] + be1[t];
        hmid[t] = siluf_(v);
        __syncthreads();
        acc = b2[t];
        #pragma unroll 8
        for (int k = 0; k < 64; k++) acc += hmid[k]*w2t[k*64+t];
        mu = red64(acc, sbuf, t) * (1.f/64.f);
        d = acc - mu;
        var = red64(d*d, sbuf, t) * (1.f/64.f);
        v = d*rsqrtf(var+1e-5f)*g2[t] + be2[t];
        outp[(size_t)e*64 + t] = siluf_(v);
        __syncthreads();
    }
}

// ========== tf32 tensor-core GEMM: C[M,N] = A[M,K] @ W[N,K]^T (+bias) =======
// CTA tile 256x128, 8 warps (4x2), warp tile m64n64, BK=16.
// Double-buffered smem with register prefetch. N%128==0, K%16==0 required.
// Dynamic smem: As[2][16][264] + Bs[2][16][136] = 51200 bytes.
#define GT_ASTRIDE 264
#define GT_BSTRIDE 136
#define GT_BOFF    (2*16*GT_ASTRIDE)
#define GT_SMEM    ((2*16*GT_ASTRIDE + 2*16*GT_BSTRIDE)*4)

__global__ void __launch_bounds__(256) k_gemm_t(
        const float* __restrict__ A, int lda,
        const float* __restrict__ W,
        const float* __restrict__ bias,
        float* __restrict__ C, int ldc, int M, int N, int K)
{
    extern __shared__ __align__(16) float smem[];
    float (*As)[16][GT_ASTRIDE] = (float(*)[16][GT_ASTRIDE])smem;
    float (*Bs)[16][GT_BSTRIDE] = (float(*)[16][GT_BSTRIDE])(smem + GT_BOFF);
    const int tid = threadIdx.x;
    const int bm = blockIdx.x*256, bn = blockIdx.y*128;
    const int wid = tid >> 5, lane = tid & 31;
    const int wm = wid & 3, wn = wid >> 2;        // 4 x 2 warps, warp tile m64 n64
    const int g = lane >> 2, q = lane & 3;
    const int srow = tid >> 2, sq4 = tid & 3;     // staging: 4 float4 per thread (A)

    float acc[4][8][4];
    #pragma unroll
    for (int i=0;i<4;i++)
        #pragma unroll
        for (int j=0;j<8;j++)
            #pragma unroll
            for (int r=0;r<4;r++) acc[i][j][r] = 0.f;

    // staging helpers: A rows bm+srow+64*i (i<4), B rows bn+srow (srow<64? no:)
    // A: 256 rows, 4 passes of 64 rows; B: 128 rows, 2 passes of 64 rows.
    #define STAGE_A(buf, k0) { \
        _Pragma("unroll") \
        for (int i = 0; i < 4; i++) { \
            int row = srow + 64*i; \
            float4 v = make_float4(0.f,0.f,0.f,0.f); \
            if (bm + row < M) v = *(const float4*)(A + (size_t)(bm+row)*lda + (k0) + sq4*4); \
            As[buf][sq4*4+0][row]=tf32f_(v.x); As[buf][sq4*4+1][row]=tf32f_(v.y); \
            As[buf][sq4*4+2][row]=tf32f_(v.z); As[buf][sq4*4+3][row]=tf32f_(v.w); \
        } }
    #define STAGE_B(buf, k0) { \
        _Pragma("unroll") \
        for (int i = 0; i < 2; i++) { \
            int row = srow + 64*i; \
            float4 v = *(const float4*)(W + (size_t)(bn+row)*K + (k0) + sq4*4); \
            Bs[buf][sq4*4+0][row]=v.x; Bs[buf][sq4*4+1][row]=v.y; \
            Bs[buf][sq4*4+2][row]=v.z; Bs[buf][sq4*4+3][row]=v.w; \
        } }

    STAGE_A(0, 0)
    STAGE_B(0, 0)
    __syncthreads();

    const int nit = K >> 4;
    int buf = 0;
    for (int it = 0; it < nit; it++) {
        // register prefetch of next tile
        float4 pa[4], pb[2];
        const bool more = (it + 1 < nit);
        if (more) {
            int k0 = (it + 1) << 4;
            #pragma unroll
            for (int i = 0; i < 4; i++) {
                int row = srow + 64*i;
                pa[i] = make_float4(0.f,0.f,0.f,0.f);
                if (bm + row < M) pa[i] = *(const float4*)(A + (size_t)(bm+row)*lda + k0 + sq4*4);
            }
            #pragma unroll
            for (int i = 0; i < 2; i++) {
                int row = srow + 64*i;
                pb[i] = *(const float4*)(W + (size_t)(bn+row)*K + k0 + sq4*4);
            }
        }
        // MMA on current buffer
        #pragma unroll
        for (int ks = 0; ks < 16; ks += 8) {
            unsigned af[4][4];
            #pragma unroll
            for (int mt=0; mt<4; mt++){
                int mb = wm*64 + mt*16;
                af[mt][0] = __float_as_uint(As[buf][ks+q  ][mb+g  ]);
                af[mt][1] = __float_as_uint(As[buf][ks+q  ][mb+g+8]);
                af[mt][2] = __float_as_uint(As[buf][ks+q+4][mb+g  ]);
                af[mt][3] = __float_as_uint(As[buf][ks+q+4][mb+g+8]);
            }
            unsigned bf[8][2];
            #pragma unroll
            for (int nt=0; nt<8; nt++){
                int nb = wn*64 + nt*8;
                bf[nt][0] = __float_as_uint(Bs[buf][ks+q  ][nb+g]);
                bf[nt][1] = __float_as_uint(Bs[buf][ks+q+4][nb+g]);
            }
            #pragma unroll
            for (int mt=0; mt<4; mt++)
                #pragma unroll
                for (int nt=0; nt<8; nt++)
                    mma8(acc[mt][nt], af[mt], bf[nt]);
        }
        if (more) {
            int nb2 = buf ^ 1;
            #pragma unroll
            for (int i = 0; i < 4; i++) {
                int row = srow + 64*i;
                As[nb2][sq4*4+0][row]=tf32f_(pa[i].x); As[nb2][sq4*4+1][row]=tf32f_(pa[i].y);
                As[nb2][sq4*4+2][row]=tf32f_(pa[i].z); As[nb2][sq4*4+3][row]=tf32f_(pa[i].w);
            }
            #pragma unroll
            for (int i = 0; i < 2; i++) {
                int row = srow + 64*i;
                Bs[nb2][sq4*4+0][row]=pb[i].x; Bs[nb2][sq4*4+1][row]=pb[i].y;
                Bs[nb2][sq4*4+2][row]=pb[i].z; Bs[nb2][sq4*4+3][row]=pb[i].w;
            }
            __syncthreads();
            buf = nb2;
        }
    }
    // epilogue
    #pragma unroll
    for (int nt=0; nt<8; nt++) {
        int c = bn + wn*64 + nt*8 + q*2;
        float2 bv = make_float2(0.f, 0.f);
        if (bias) bv = *(const float2*)(bias + c);
        #pragma unroll
        for (int mt=0; mt<4; mt++) {
            int r0 = bm + wm*64 + mt*16 + g;
            if (r0 < M) {
                float2 o = make_float2(acc[mt][nt][0]+bv.x, acc[mt][nt][1]+bv.y);
                *(float2*)(C + (size_t)r0*ldc + c) = o;
            }
            if (r0 + 8 < M) {
                float2 o = make_float2(acc[mt][nt][2]+bv.x, acc[mt][nt][3]+bv.y);
                *(float2*)(C + (size_t)(r0+8)*ldc + c) = o;
            }
        }
    }
}

// ---------- wigner: msg = perm(wigner @ [x_src|x_dst]) * rad ----------------
__global__ void k_wigner(const float* __restrict__ x, const int* __restrict__ ei,
                         const float* __restrict__ wig, const float* __restrict__ rad,
                         float* __restrict__ sm)
{
    __shared__ float msg[25][128];
    __shared__ float wg[19][25];
    int e = blockIdx.x;
    int t = threadIdx.x; // 128
    int src = ei[e], dst = ei[NE + e];
    const float* xs = x + (size_t)src*1600;
    const float* xd = x + (size_t)dst*1600;
    int c = t & 63;
    if (t < 64) { for (int j=0;j<25;j++) msg[j][t] = xs[j*64+c]; }
    else        { for (int j=0;j<25;j++) msg[j][t] = xd[j*64+c]; }
    for (int i = t; i < 475; i += 128) {
        int p = i/25, j = i%25;
        wg[p][j] = wig[(size_t)e*475 + (size_t)c_PERM[p]*25 + j];
    }
    __syncthreads();
    const float* re = rad + (size_t)e*1536;
    float* so = sm + (size_t)e*2432;
    #pragma unroll
    for (int p = 0; p < 19; p++) {
        float acc = 0.f;
        #pragma unroll
        for (int j = 0; j < 25; j++) acc += wg[p][j]*msg[j][t];
        so[p*128 + t] = acc * re[c_RADOFF[p] + t];
    }
}

// ---------- grid stage: silu-gated S2 pointwise -----------------------------
__global__ void k_grid(const float* __restrict__ tmp0, const float* __restrict__ h1,
                       const float* __restrict__ tgrid, const float* __restrict__ fgrid,
                       float* __restrict__ h2)
{
    __shared__ float tg[100][20];
    __shared__ float fg[100][20];
    __shared__ float h[2][19][64];
    int t = threadIdx.x; // 128
    for (int i = t; i < 1900; i += 128) {
        int ba = i / 19, p = i % 19;
        tg[ba][p] = tgrid[ba*19 + c_PERM[p]];
        fg[ba][p] = fgrid[ba*19 + c_PERM[p]];
    }
    int el = t >> 6, c = t & 63;
    int e = blockIdx.x*2 + el;
    const float* t0 = tmp0 + (size_t)e*896;
    #pragma unroll
    for (int p = 0; p < 5; p++) h[el][p][c] = t0[576 + p*64 + c];
    const float* hh = h1 + (size_t)e*1216;
    #pragma unroll
    for (int p = 5; p < 19; p++) h[el][p][c] = hh[p*64 + c];
    __syncthreads();
    float s2[19];
    #pragma unroll
    for (int p=0;p<19;p++) s2[p]=0.f;
    for (int ba = 0; ba < 100; ba++) {
        float g = 0.f;
        #pragma unroll
        for (int p = 0; p < 19; p++) g += tg[ba][p]*h[el][p][c];
        g = siluf_(g);
        #pragma unroll
        for (int p = 0; p < 19; p++) s2[p] += fg[ba][p]*g;
    }
    float* o = h2 + (size_t)e*1216;
    o[c] = siluf_(t0[512 + c]);          // row 0 := silu(gate)
    #pragma unroll
    for (int p = 1; p < 19; p++) o[p*64 + c] = s2[p];
}

// ---------- alpha: LN + smooth-leaky-relu + dot, atomicMax ------------------
__global__ void k_alpha1(const float* __restrict__ tmp0, const int* __restrict__ ei,
                         const float* __restrict__ lng, const float* __restrict__ lnb,
                         const float* __restrict__ adot,
                         float* __restrict__ alpha, unsigned int* __restrict__ amax)
{
    int e = blockIdx.x;
    int w = threadIdx.x >> 5, lane = threadIdx.x & 31; // 8 warps = 8 heads
    const float* a = tmp0 + (size_t)e*896 + w*64;
    float v0 = a[lane], v1 = a[lane+32];
    float s = v0+v1;
    #pragma unroll
    for (int o=16;o;o>>=1) s += __shfl_xor_sync(0xffffffffu, s, o);
    float mu = s * (1.f/64.f);
    float d0=v0-mu, d1=v1-mu;
    float q = d0*d0+d1*d1;
    #pragma unroll
    for (int o=16;o;o>>=1) q += __shfl_xor_sync(0xffffffffu, q, o);
    float rstd = rsqrtf(q*(1.f/64.f) + 1e-5f);
    float x0 = slrelu_(d0*rstd*lng[lane]+lnb[lane]);
    float x1 = slrelu_(d1*rstd*lng[lane+32]+lnb[lane+32]);
    float p = x0*adot[w*64+lane] + x1*adot[w*64+lane+32];
    #pragma unroll
    for (int o=16;o;o>>=1) p += __shfl_xor_sync(0xffffffffu, p, o);
    if (lane == 0) {
        alpha[e*8+w] = p;
        int dst = ei[NE + e];
        unsigned int enc = __float_as_uint(p);
        enc = (enc & 0x80000000u) ? ~enc : (enc | 0x80000000u);
        atomicMax(&amax[dst*8+w], enc);
    }
}

__global__ void k_alpha2(float* __restrict__ alpha, const int* __restrict__ ei,
                         const unsigned int* __restrict__ amax, float* __restrict__ den)
{
    int i = blockIdx.x*256 + threadIdx.x;
    if (i >= NE*8) return;
    int e = i >> 3, h = i & 7;
    int dst = ei[NE + e];
    unsigned int u = amax[dst*8+h];
    float m = (u & 0x80000000u) ? __uint_as_float(u & 0x7FFFFFFFu) : __uint_as_float(~u);
    float ex = __expf(alpha[i] - m);
    alpha[i] = ex;
    atomicAdd(&den[dst*8+h], ex);
}

// ---------- attention weight + wigner_inv + segment-sum ---------------------
__global__ void k_attn(const float* __restrict__ h3, const float* __restrict__ winv,
                       const float* __restrict__ alpha, const float* __restrict__ den,
                       const int* __restrict__ ei, float* __restrict__ node)
{
    __shared__ float m[19][128];
    __shared__ float wi[25][20];
    __shared__ float wt[8];
    int e = blockIdx.x, t = threadIdx.x; // 128
    int dst = ei[NE + e];
    if (t < 8) wt[t] = alpha[e*8+t] / (den[dst*8+t] + 1e-16f);
    for (int i = t; i < 475; i += 128) {
        int r = i/19, p = i%19;
        wi[r][p] = winv[(size_t)e*475 + r*19 + c_PERM[p]];
    }
    __syncthreads();
    const float* hh = h3 + (size_t)e*2432;
    float w = wt[t >> 4];
    #pragma unroll
    for (int p = 0; p < 19; p++) m[p][t] = hh[p*128 + t] * w;
    __syncthreads();
    float* no = node + (size_t)dst*3200;
    #pragma unroll
    for (int r = 0; r < 25; r++) {
        float acc = 0.f;
        #pragma unroll
        for (int p = 0; p < 19; p++) acc += wi[r][p]*m[p][t];
        atomicAdd(&no[r*128 + t], acc);
    }
}

// ---------- output projection ----------------------------------------------
__global__ void k_proj(const float* __restrict__ node, const float* __restrict__ pw,
                       const float* __restrict__ pb, float* __restrict__ outp)
{
    __shared__ float wt[128*65];
    int bid = blockIdx.x;      // n*5 + l
    int n = bid / 5, l = bid % 5;
    int t = threadIdx.x;       // 64
    for (int i = t; i < 8192; i += 64) {
        int o = i >> 7, c = i & 127;
        wt[c*65 + o] = pw[l*8192 + i];
    }
    __syncthreads();
    int i0 = l*l, i1 = (l+1)*(l+1);
    for (int i = i0; i < i1; i++) {
        const float* nr = node + (size_t)n*3200 + i*128;
        float acc = (i == 0) ? pb[t] : 0.f;
        #pragma unroll 8
        for (int c = 0; c < 128; c++) acc += nr[c] * wt[c*65 + t];
        outp[(size_t)n*1600 + i*64 + t] = acc;
    }
}

// ----------------------------------------------------------------------------
extern "C" void kernel_launch(void* const* d_in, const int* in_sizes, int n_in,
                              void* d_out, int out_size)
{
    const float* x    = (const float*)d_in[0];
    const float* ed   = (const float*)d_in[1];
    const int*   ei   = (const int*)  d_in[2];
    const float* wig  = (const float*)d_in[3];
    const float* winv = (const float*)d_in[4];
    const float* tgr  = (const float*)d_in[5];
    const float* fgr  = (const float*)d_in[6];
    const float* rw1  = (const float*)d_in[7];
    const float* rb1  = (const float*)d_in[8];
    const float* rg1  = (const float*)d_in[9];
    const float* rbe1 = (const float*)d_in[10];
    const float* rw2  = (const float*)d_in[11];
    const float* rb2  = (const float*)d_in[12];
    const float* rg2  = (const float*)d_in[13];
    const float* rbe2 = (const float*)d_in[14];
    const float* rw3  = (const float*)d_in[15];
    const float* rb3  = (const float*)d_in[16];
    const float* c1w0 = (const float*)d_in[17];
    const float* c1b0 = (const float*)d_in[18];
    const float* c1w1 = (const float*)d_in[19];
    const float* c1w2 = (const float*)d_in[20];
    const float* c2w0 = (const float*)d_in[21];
    const float* c2b0 = (const float*)d_in[22];
    const float* c2w1 = (const float*)d_in[23];
    const float* c2w2 = (const float*)d_in[24];
    const float* alng = (const float*)d_in[25];
    const float* alnb = (const float*)d_in[26];
    const float* adot = (const float*)d_in[27];
    const float* pw   = (const float*)d_in[28];
    const float* pb   = (const float*)d_in[29];
    float* outp = (float*)d_out;

    void* p;
    cudaGetSymbolAddress(&p, g_hid);  float* hid  = (float*)p;
    cudaGetSymbolAddress(&p, g_rad);  float* rad  = (float*)p;
    cudaGetSymbolAddress(&p, g_sm);   float* sm   = (float*)p;
    cudaGetSymbolAddress(&p, g_tmp0); float* tmp0 = (float*)p;
    cudaGetSymbolAddress(&p, g_h1);   float* h1   = (float*)p;
    cudaGetSymbolAddress(&p, g_h2);   float* h2   = (float*)p;
    cudaGetSymbolAddress(&p, g_h3);   float* h3   = (float*)p;
    cudaGetSymbolAddress(&p, g_alf);  float* alf  = (float*)p;
    cudaGetSymbolAddress(&p, g_amax); unsigned int* amax = (unsigned int*)p;
    cudaGetSymbolAddress(&p, g_den);  float* den  = (float*)p;
    cudaGetSymbolAddress(&p, g_node); float* node = (float*)p;
    cudaGetSymbolAddress(&p, g_wp);   float* wp   = (float*)p;

    cudaFuncSetAttribute(k_gemm_t, cudaFuncAttributeMaxDynamicSharedMemorySize, GT_SMEM);

    const int MB = (NE + 255) / 256;   // 79

    k_init<<<(NN*3200 + 255)/256, 256>>>(node, amax, den);

    // weight prep (tf32 round; complex weights expanded to real form)
    k_cvtw<<<(98304+255)/256, 256>>>(rw3,  wp + WP_RAD,  98304);
    k_cvtw<<<(573440+255)/256, 256>>>(c1w0, wp + WP_C1G0, 573440);
    k_cvtw<<<(204800+255)/256, 256>>>(c2w0, wp + WP_C2G0, 204800);
    k_prepw<<<(256*512+255)/256, 256>>>(c1w1, wp + WP_C1M1, 256, 512);
    k_prepw<<<(192*384+255)/256, 256>>>(c1w2, wp + WP_C1M2, 192, 384);
    k_prepw<<<(512*256+255)/256, 256>>>(c2w1, wp + WP_C2M1, 512, 256);
    k_prepw<<<(384*192+255)/256, 256>>>(c2w2, wp + WP_C2M2, 384, 192);

    k_radial<<<512, 64>>>(ed, rw1, rb1, rg1, rbe1, rw2, rb2, rg2, rbe2, hid);
    k_gemm_t<<<dim3(MB, 12), 256, GT_SMEM>>>(hid, 64, wp + WP_RAD, rb3, rad, 1536, NE, 1536, 64);
    k_wigner<<<NE, 128>>>(x, ei, wig, rad, sm);
    // conv1
    k_gemm_t<<<dim3(MB, 7), 256, GT_SMEM>>>(sm, 2432, wp + WP_C1G0, c1b0, tmp0, 896, NE, 896, 640);
    k_gemm_t<<<dim3(MB, 4), 256, GT_SMEM>>>(sm+640,  2432, wp + WP_C1M1, nullptr, h1+320, 1216, NE, 512, 1024);
    k_gemm_t<<<dim3(MB, 3), 256, GT_SMEM>>>(sm+1664, 2432, wp + WP_C1M2, nullptr, h1+832, 1216, NE, 384, 768);
    // grid nonlinearity
    k_grid<<<NE/2, 128>>>(tmp0, h1, tgr, fgr, h2);
    // conv2
    k_gemm_t<<<dim3(MB, 5), 256, GT_SMEM>>>(h2, 1216, wp + WP_C2G0, c2b0, h3, 2432, NE, 640, 320);
    k_gemm_t<<<dim3(MB, 8), 256, GT_SMEM>>>(h2+320, 1216, wp + WP_C2M1, nullptr, h3+640,  2432, NE, 1024, 512);
    k_gemm_t<<<dim3(MB, 6), 256, GT_SMEM>>>(h2+832, 1216, wp + WP_C2M2, nullptr, h3+1664, 2432, NE, 768, 384);
    // attention
    k_alpha1<<<NE, 256>>>(tmp0, ei, alng, alnb, adot, alf, amax);
    k_alpha2<<<(NE*8 + 255)/256, 256>>>(alf, ei, amax, den);
    k_attn<<<NE, 128>>>(h3, winv, alf, den, ei, node);
    // projection
    k_proj<<<NN*5, 64>>>(node, pw, pb, outp);
}

// round 9
// speedup vs baseline: 2.2278x; 1.2201x over previous
#include <cuda_runtime.h>
#include <cuda_fp16.h>
#include <cuda_bf16.h>
#include <cstdint>

#define NE 20000
#define NN 1000

// permuted row order: m=0 rows(5), +1(4), -1(4), +2(3), -2(3)
__constant__ int c_PERM[19]   = {0,2,6,11,16, 3,7,12,17, 1,5,10,15, 8,13,18, 4,9,14};
__constant__ int c_RADOFF[19] = {0,128,256,384,512, 640,768,896,1024, 640,768,896,1024,
                                 1152,1280,1408, 1152,1280,1408};

// ----------------- scratch (__device__ globals; no runtime alloc) -----------
__device__ __align__(16) float g_hid [(size_t)NE*64];
__device__ __align__(16) float g_rad [(size_t)NE*1536];
__device__ __align__(16) float g_sm  [(size_t)NE*2432];   // wigner out, permuted, rad-scaled
__device__ __align__(16) float g_tmp0[(size_t)NE*896];    // conv1 gemm0 out (alpha|gate|m0)
__device__ __align__(16) float g_h1  [(size_t)NE*1216];   // conv1 out rows 5..18 (64/row)
__device__ __align__(16) float g_h2  [(size_t)NE*1216];   // grid-stage out (19x64 permuted)
__device__ __align__(16) float g_h3  [(size_t)NE*2432];   // conv2 out (19x128 permuted)
__device__ __align__(16) float g_alf [(size_t)NE*8];
__device__ unsigned int        g_amax[NN*8];
__device__ float               g_den [NN*8];
__device__ __align__(16) float g_node[(size_t)NN*3200];
// fp16-prepped weights (plain + complex-expanded), element offsets below
__device__ __align__(16) __half g_wp [2514944];

// offsets into g_wp (element counts)
#define WP_RAD   0
#define WP_C1G0  98304
#define WP_C1M1  671744
#define WP_C1M2  1196032
#define WP_C2G0  1490944
#define WP_C2M1  1695744
#define WP_C2M2  2220032

// ----------------- helpers --------------------------------------------------
__device__ __forceinline__ float sigmoidf_(float x){ return 1.f/(1.f+__expf(-x)); }
__device__ __forceinline__ float siluf_(float x){ return x*sigmoidf_(x); }
__device__ __forceinline__ float slrelu_(float x){ return 0.6f*x + 0.4f*x*(2.f*sigmoidf_(x)-1.f); }

// m16n8k16 fp16 mma, fp32 accumulate
__device__ __forceinline__ void mma16h(float* d, const unsigned* a, const unsigned* b){
    asm("mma.sync.aligned.m16n8k16.row.col.f32.f16.f16.f32 "
        "{%0,%1,%2,%3}, {%4,%5,%6,%7}, {%8,%9}, {%0,%1,%2,%3};"
        : "+f"(d[0]), "+f"(d[1]), "+f"(d[2]), "+f"(d[3])
        : "r"(a[0]), "r"(a[1]), "r"(a[2]), "r"(a[3]), "r"(b[0]), "r"(b[1]));
}

__device__ __forceinline__ unsigned pack_h2(float a, float b){
    __half2 h = __floats2half2_rn(a, b);
    return *(unsigned*)&h;
}

// reduce over 64 threads (2 warps), blockDim==64
__device__ __forceinline__ float red64(float v, float* sbuf, int t){
    #pragma unroll
    for (int o=16;o;o>>=1) v += __shfl_xor_sync(0xffffffffu, v, o);
    if ((t&31)==0) sbuf[t>>5] = v;
    __syncthreads();
    float r = sbuf[0]+sbuf[1];
    __syncthreads();
    return r;
}

// ----------------- init -----------------------------------------------------
__global__ void k_init(float* node, unsigned int* amax, float* den){
    int i = blockIdx.x*256 + threadIdx.x;
    if (i < NN*3200) node[i] = 0.f;
    if (i < NN*8) { amax[i] = 0u; den[i] = 0.f; }
}

// ----------------- weight prep ----------------------------------------------
__global__ void k_cvtw(const float* __restrict__ w, __half* __restrict__ o, int n){
    int i = blockIdx.x*256 + threadIdx.x;
    if (i < n) o[i] = __float2half_rn(w[i]);
}
// complex: w[(2N)xK] (rows 0..N-1 = Wr, N..2N-1 = Wi) ->
// wp[(2N)x(2K)]: row n = [Wr[n] | -Wi[n]], row N+n = [Wi[n] | Wr[n]]
__global__ void k_prepw(const float* __restrict__ w, __half* __restrict__ wp, int N, int K){
    int i = blockIdx.x*256 + threadIdx.x;
    if (i >= N*K) return;
    int n = i / K, k = i % K;
    float wr = w[(size_t)n*K + k];
    float wi = w[(size_t)(N+n)*K + k];
    size_t row0 = (size_t)n*2*K, row1 = (size_t)(N+n)*2*K;
    wp[row0 + k]     = __float2half_rn(wr);
    wp[row0 + K + k] = __float2half_rn(-wi);
    wp[row1 + k]     = __float2half_rn(wi);
    wp[row1 + K + k] = __float2half_rn(wr);
}

// ----------------- radial layers 1+2 (LN + silu) ----------------------------
__global__ void k_radial(const float* __restrict__ ed,
                         const float* __restrict__ w1, const float* __restrict__ b1,
                         const float* __restrict__ g1, const float* __restrict__ be1,
                         const float* __restrict__ w2, const float* __restrict__ b2,
                         const float* __restrict__ g2, const float* __restrict__ be2,
                         float* __restrict__ outp)
{
    __shared__ float w1t[64*64], w2t[64*64];
    __shared__ float xin[64], hmid[64];
    __shared__ float sbuf[2];
    int t = threadIdx.x; // 64
    for (int i = t; i < 4096; i += 64) {
        int r = i >> 6, c = i & 63;
        w1t[c*64 + r] = w1[i];
        w2t[c*64 + r] = w2[i];
    }
    __syncthreads();
    for (int e = blockIdx.x; e < NE; e += gridDim.x) {
        xin[t] = ed[(size_t)e*64 + t];
        __syncthreads();
        float acc = b1[t];
        #pragma unroll 8
        for (int k = 0; k < 64; k++) acc += xin[k]*w1t[k*64+t];
        float mu = red64(acc, sbuf, t) * (1.f/64.f);
        float d = acc - mu;
        float var = red64(d*d, sbuf, t) * (1.f/64.f);
        float v = d*rsqrtf(var+1e-5f)*g1[t] + be1[t];
        hmid[t] = siluf_(v);
        __syncthreads();
        acc = b2[t];
        #pragma unroll 8
        for (int k = 0; k < 64; k++) acc += hmid[k]*w2t[k*64+t];
        mu = red64(acc, sbuf, t) * (1.f/64.f);
        d = acc - mu;
        var = red64(d*d, sbuf, t) * (1.f/64.f);
        v = d*rsqrtf(var+1e-5f)*g2[t] + be2[t];
        outp[(size_t)e*64 + t] = siluf_(v);
        __syncthreads();
    }
}

// ======= fp16 tensor-core GEMM: C[M,N] = A[M,K] @ W[N,K]^T (+bias) ==========
// CTA tile 256x128, 8 warps (4x2), warp tile m64n64, BK=16 (k16 mma).
// smem: half2, layout [k2][row]; strides keep all fragment banks distinct.
// Double-buffered with register prefetch. N%128==0, K%16==0 required.
#define GH_ASTRIDE 264
#define GH_BSTRIDE 136
#define GH_BOFF    (2*8*GH_ASTRIDE)
#define GH_SMEM    ((2*8*GH_ASTRIDE + 2*8*GH_BSTRIDE)*4)

__global__ void __launch_bounds__(256) k_gemm_h(
        const float* __restrict__ A, int lda,
        const __half* __restrict__ W,
        const float* __restrict__ bias,
        float* __restrict__ C, int ldc, int M, int N, int K)
{
    extern __shared__ __align__(16) unsigned smemu[];
    unsigned (*As2)[8][GH_ASTRIDE] = (unsigned(*)[8][GH_ASTRIDE])smemu;
    unsigned (*Bs2)[8][GH_BSTRIDE] = (unsigned(*)[8][GH_BSTRIDE])(smemu + GH_BOFF);
    const int tid = threadIdx.x;
    const int bm = blockIdx.x*256, bn = blockIdx.y*128;
    const int wid = tid >> 5, lane = tid & 31;
    const int wm = wid & 3, wn = wid >> 2;        // 4 x 2 warps, warp tile m64 n64
    const int g = lane >> 2, q = lane & 3;
    const int srow = tid >> 2, sq4 = tid & 3;     // staging

    float acc[4][8][4];
    #pragma unroll
    for (int i=0;i<4;i++)
        #pragma unroll
        for (int j=0;j<8;j++)
            #pragma unroll
            for (int r=0;r<4;r++) acc[i][j][r] = 0.f;

    #define HSTAGE_A(buf, k0) { \
        _Pragma("unroll") \
        for (int i = 0; i < 4; i++) { \
            int row = srow + 64*i; \
            float4 v = make_float4(0.f,0.f,0.f,0.f); \
            if (bm + row < M) v = *(const float4*)(A + (size_t)(bm+row)*lda + (k0) + sq4*4); \
            As2[buf][sq4*2+0][row] = pack_h2(v.x, v.y); \
            As2[buf][sq4*2+1][row] = pack_h2(v.z, v.w); \
        } }
    #define HSTAGE_B(buf, k0) { \
        _Pragma("unroll") \
        for (int i = 0; i < 2; i++) { \
            int row = srow + 64*i; \
            uint2 v = *(const uint2*)(W + (size_t)(bn+row)*K + (k0) + sq4*4); \
            Bs2[buf][sq4*2+0][row] = v.x; \
            Bs2[buf][sq4*2+1][row] = v.y; \
        } }

    HSTAGE_A(0, 0)
    HSTAGE_B(0, 0)
    __syncthreads();

    const int nit = K >> 4;
    int buf = 0;
    for (int it = 0; it < nit; it++) {
        // register prefetch of next tile
        float4 pa[4]; uint2 pb[2];
        const bool more = (it + 1 < nit);
        if (more) {
            int k0 = (it + 1) << 4;
            #pragma unroll
            for (int i = 0; i < 4; i++) {
                int row = srow + 64*i;
                pa[i] = make_float4(0.f,0.f,0.f,0.f);
                if (bm + row < M) pa[i] = *(const float4*)(A + (size_t)(bm+row)*lda + k0 + sq4*4);
            }
            #pragma unroll
            for (int i = 0; i < 2; i++) {
                int row = srow + 64*i;
                pb[i] = *(const uint2*)(W + (size_t)(bn+row)*K + k0 + sq4*4);
            }
        }
        // MMA on current buffer: one k16 pass
        {
            unsigned af[4][4];
            #pragma unroll
            for (int mt=0; mt<4; mt++){
                int mb = wm*64 + mt*16;
                af[mt][0] = As2[buf][q  ][mb+g  ];
                af[mt][1] = As2[buf][q  ][mb+g+8];
                af[mt][2] = As2[buf][q+4][mb+g  ];
                af[mt][3] = As2[buf][q+4][mb+g+8];
            }
            unsigned bf[8][2];
            #pragma unroll
            for (int nt=0; nt<8; nt++){
                int nb = wn*64 + nt*8;
                bf[nt][0] = Bs2[buf][q  ][nb+g];
                bf[nt][1] = Bs2[buf][q+4][nb+g];
            }
            #pragma unroll
            for (int mt=0; mt<4; mt++)
                #pragma unroll
                for (int nt=0; nt<8; nt++)
                    mma16h(acc[mt][nt], af[mt], bf[nt]);
        }
        if (more) {
            int nb2 = buf ^ 1;
            #pragma unroll
            for (int i = 0; i < 4; i++) {
                int row = srow + 64*i;
                As2[nb2][sq4*2+0][row] = pack_h2(pa[i].x, pa[i].y);
                As2[nb2][sq4*2+1][row] = pack_h2(pa[i].z, pa[i].w);
            }
            #pragma unroll
            for (int i = 0; i < 2; i++) {
                int row = srow + 64*i;
                Bs2[nb2][sq4*2+0][row] = pb[i].x;
                Bs2[nb2][sq4*2+1][row] = pb[i].y;
            }
            __syncthreads();
            buf = nb2;
        }
    }
    // epilogue
    #pragma unroll
    for (int nt=0; nt<8; nt++) {
        int c = bn + wn*64 + nt*8 + q*2;
        float2 bv = make_float2(0.f, 0.f);
        if (bias) bv = *(const float2*)(bias + c);
        #pragma unroll
        for (int mt=0; mt<4; mt++) {
            int r0 = bm + wm*64 + mt*16 + g;
            if (r0 < M) {
                float2 o = make_float2(acc[mt][nt][0]+bv.x, acc[mt][nt][1]+bv.y);
                *(float2*)(C + (size_t)r0*ldc + c) = o;
            }
            if (r0 + 8 < M) {
                float2 o = make_float2(acc[mt][nt][2]+bv.x, acc[mt][nt][3]+bv.y);
                *(float2*)(C + (size_t)(r0+8)*ldc + c) = o;
            }
        }
    }
}

// ---------- wigner: msg = perm(wigner @ [x_src|x_dst]) * rad ----------------
__global__ void k_wigner(const float* __restrict__ x, const int* __restrict__ ei,
                         const float* __restrict__ wig, const float* __restrict__ rad,
                         float* __restrict__ sm)
{
    __shared__ float msg[25][128];
    __shared__ float wg[19][25];
    int e = blockIdx.x;
    int t = threadIdx.x; // 128
    int src = ei[e], dst = ei[NE + e];
    const float* xs = x + (size_t)src*1600;
    const float* xd = x + (size_t)dst*1600;
    int c = t & 63;
    if (t < 64) { for (int j=0;j<25;j++) msg[j][t] = xs[j*64+c]; }
    else        { for (int j=0;j<25;j++) msg[j][t] = xd[j*64+c]; }
    for (int i = t; i < 475; i += 128) {
        int p = i/25, j = i%25;
        wg[p][j] = wig[(size_t)e*475 + (size_t)c_PERM[p]*25 + j];
    }
    __syncthreads();
    const float* re = rad + (size_t)e*1536;
    float* so = sm + (size_t)e*2432;
    #pragma unroll
    for (int p = 0; p < 19; p++) {
        float acc = 0.f;
        #pragma unroll
        for (int j = 0; j < 25; j++) acc += wg[p][j]*msg[j][t];
        so[p*128 + t] = acc * re[c_RADOFF[p] + t];
    }
}

// ---------- grid stage: silu-gated S2 pointwise -----------------------------
__global__ void k_grid(const float* __restrict__ tmp0, const float* __restrict__ h1,
                       const float* __restrict__ tgrid, const float* __restrict__ fgrid,
                       float* __restrict__ h2)
{
    __shared__ float tg[100][20];
    __shared__ float fg[100][20];
    __shared__ float h[2][19][64];
    int t = threadIdx.x; // 128
    for (int i = t; i < 1900; i += 128) {
        int ba = i / 19, p = i % 19;
        tg[ba][p] = tgrid[ba*19 + c_PERM[p]];
        fg[ba][p] = fgrid[ba*19 + c_PERM[p]];
    }
    int el = t >> 6, c = t & 63;
    int e = blockIdx.x*2 + el;
    const float* t0 = tmp0 + (size_t)e*896;
    #pragma unroll
    for (int p = 0; p < 5; p++) h[el][p][c] = t0[576 + p*64 + c];
    const float* hh = h1 + (size_t)e*1216;
    #pragma unroll
    for (int p = 5; p < 19; p++) h[el][p][c] = hh[p*64 + c];
    __syncthreads();
    float s2[19];
    #pragma unroll
    for (int p=0;p<19;p++) s2[p]=0.f;
    for (int ba = 0; ba < 100; ba++) {
        float g = 0.f;
        #pragma unroll
        for (int p = 0; p < 19; p++) g += tg[ba][p]*h[el][p][c];
        g = siluf_(g);
        #pragma unroll
        for (int p = 0; p < 19; p++) s2[p] += fg[ba][p]*g;
    }
    float* o = h2 + (size_t)e*1216;
    o[c] = siluf_(t0[512 + c]);          // row 0 := silu(gate)
    #pragma unroll
    for (int p = 1; p < 19; p++) o[p*64 + c] = s2[p];
}

// ---------- alpha: LN + smooth-leaky-relu + dot, atomicMax ------------------
__global__ void k_alpha1(const float* __restrict__ tmp0, const int* __restrict__ ei,
                         const float* __restrict__ lng, const float* __restrict__ lnb,
                         const float* __restrict__ adot,
                         float* __restrict__ alpha, unsigned int* __restrict__ amax)
{
    int e = blockIdx.x;
    int w = threadIdx.x >> 5, lane = threadIdx.x & 31; // 8 warps = 8 heads
    const float* a = tmp0 + (size_t)e*896 + w*64;
    float v0 = a[lane], v1 = a[lane+32];
    float s = v0+v1;
    #pragma unroll
    for (int o=16;o;o>>=1) s += __shfl_xor_sync(0xffffffffu, s, o);
    float mu = s * (1.f/64.f);
    float d0=v0-mu, d1=v1-mu;
    float q = d0*d0+d1*d1;
    #pragma unroll
    for (int o=16;o;o>>=1) q += __shfl_xor_sync(0xffffffffu, q, o);
    float rstd = rsqrtf(q*(1.f/64.f) + 1e-5f);
    float x0 = slrelu_(d0*rstd*lng[lane]+lnb[lane]);
    float x1 = slrelu_(d1*rstd*lng[lane+32]+lnb[lane+32]);
    float p = x0*adot[w*64+lane] + x1*adot[w*64+lane+32];
    #pragma unroll
    for (int o=16;o;o>>=1) p += __shfl_xor_sync(0xffffffffu, p, o);
    if (lane == 0) {
        alpha[e*8+w] = p;
        int dst = ei[NE + e];
        unsigned int enc = __float_as_uint(p);
        enc = (enc & 0x80000000u) ? ~enc : (enc | 0x80000000u);
        atomicMax(&amax[dst*8+w], enc);
    }
}

__global__ void k_alpha2(float* __restrict__ alpha, const int* __restrict__ ei,
                         const unsigned int* __restrict__ amax, float* __restrict__ den)
{
    int i = blockIdx.x*256 + threadIdx.x;
    if (i >= NE*8) return;
    int e = i >> 3, h = i & 7;
    int dst = ei[NE + e];
    unsigned int u = amax[dst*8+h];
    float m = (u & 0x80000000u) ? __uint_as_float(u & 0x7FFFFFFFu) : __uint_as_float(~u);
    float ex = __expf(alpha[i] - m);
    alpha[i] = ex;
    atomicAdd(&den[dst*8+h], ex);
}

// ---------- attention weight + wigner_inv + segment-sum ---------------------
__global__ void k_attn(const float* __restrict__ h3, const float* __restrict__ winv,
                       const float* __restrict__ alpha, const float* __restrict__ den,
                       const int* __restrict__ ei, float* __restrict__ node)
{
    __shared__ float m[19][128];
    __shared__ float wi[25][20];
    __shared__ float wt[8];
    int e = blockIdx.x, t = threadIdx.x; // 128
    int dst = ei[NE + e];
    if (t < 8) wt[t] = alpha[e*8+t] / (den[dst*8+t] + 1e-16f);
    for (int i = t; i < 475; i += 128) {
        int r = i/19, p = i%19;
        wi[r][p] = winv[(size_t)e*475 + r*19 + c_PERM[p]];
    }
    __syncthreads();
    const float* hh = h3 + (size_t)e*2432;
    float w = wt[t >> 4];
    #pragma unroll
    for (int p = 0; p < 19; p++) m[p][t] = hh[p*128 + t] * w;
    __syncthreads();
    float* no = node + (size_t)dst*3200;
    #pragma unroll
    for (int r = 0; r < 25; r++) {
        float acc = 0.f;
        #pragma unroll
        for (int p = 0; p < 19; p++) acc += wi[r][p]*m[p][t];
        atomicAdd(&no[r*128 + t], acc);
    }
}

// ---------- output projection ----------------------------------------------
__global__ void k_proj(const float* __restrict__ node, const float* __restrict__ pw,
                       const float* __restrict__ pb, float* __restrict__ outp)
{
    __shared__ float wt[128*65];
    int bid = blockIdx.x;      // n*5 + l
    int n = bid / 5, l = bid % 5;
    int t = threadIdx.x;       // 64
    for (int i = t; i < 8192; i += 64) {
        int o = i >> 7, c = i & 127;
        wt[c*65 + o] = pw[l*8192 + i];
    }
    __syncthreads();
    int i0 = l*l, i1 = (l+1)*(l+1);
    for (int i = i0; i < i1; i++) {
        const float* nr = node + (size_t)n*3200 + i*128;
        float acc = (i == 0) ? pb[t] : 0.f;
        #pragma unroll 8
        for (int c = 0; c < 128; c++) acc += nr[c] * wt[c*65 + t];
        outp[(size_t)n*1600 + i*64 + t] = acc;
    }
}

// ----------------------------------------------------------------------------
extern "C" void kernel_launch(void* const* d_in, const int* in_sizes, int n_in,
                              void* d_out, int out_size)
{
    const float* x    = (const float*)d_in[0];
    const float* ed   = (const float*)d_in[1];
    const int*   ei   = (const int*)  d_in[2];
    const float* wig  = (const float*)d_in[3];
    const float* winv = (const float*)d_in[4];
    const float* tgr  = (const float*)d_in[5];
    const float* fgr  = (const float*)d_in[6];
    const float* rw1  = (const float*)d_in[7];
    const float* rb1  = (const float*)d_in[8];
    const float* rg1  = (const float*)d_in[9];
    const float* rbe1 = (const float*)d_in[10];
    const float* rw2  = (const float*)d_in[11];
    const float* rb2  = (const float*)d_in[12];
    const float* rg2  = (const float*)d_in[13];
    const float* rbe2 = (const float*)d_in[14];
    const float* rw3  = (const float*)d_in[15];
    const float* rb3  = (const float*)d_in[16];
    const float* c1w0 = (const float*)d_in[17];
    const float* c1b0 = (const float*)d_in[18];
    const float* c1w1 = (const float*)d_in[19];
    const float* c1w2 = (const float*)d_in[20];
    const float* c2w0 = (const float*)d_in[21];
    const float* c2b0 = (const float*)d_in[22];
    const float* c2w1 = (const float*)d_in[23];
    const float* c2w2 = (const float*)d_in[24];
    const float* alng = (const float*)d_in[25];
    const float* alnb = (const float*)d_in[26];
    const float* adot = (const float*)d_in[27];
    const float* pw   = (const float*)d_in[28];
    const float* pb   = (const float*)d_in[29];
    float* outp = (float*)d_out;

    void* p;
    cudaGetSymbolAddress(&p, g_hid);  float* hid  = (float*)p;
    cudaGetSymbolAddress(&p, g_rad);  float* rad  = (float*)p;
    cudaGetSymbolAddress(&p, g_sm);   float* sm   = (float*)p;
    cudaGetSymbolAddress(&p, g_tmp0); float* tmp0 = (float*)p;
    cudaGetSymbolAddress(&p, g_h1);   float* h1   = (float*)p;
    cudaGetSymbolAddress(&p, g_h2);   float* h2   = (float*)p;
    cudaGetSymbolAddress(&p, g_h3);   float* h3   = (float*)p;
    cudaGetSymbolAddress(&p, g_alf);  float* alf  = (float*)p;
    cudaGetSymbolAddress(&p, g_amax); unsigned int* amax = (unsigned int*)p;
    cudaGetSymbolAddress(&p, g_den);  float* den  = (float*)p;
    cudaGetSymbolAddress(&p, g_node); float* node = (float*)p;
    cudaGetSymbolAddress(&p, g_wp);   __half* wp  = (__half*)p;

    cudaFuncSetAttribute(k_gemm_h, cudaFuncAttributeMaxDynamicSharedMemorySize, GH_SMEM);

    const int MB = (NE + 255) / 256;   // 79

    k_init<<<(NN*3200 + 255)/256, 256>>>(node, amax, den);

    // weight prep (fp16 round; complex weights expanded to real form)
    k_cvtw<<<(98304+255)/256, 256>>>(rw3,  wp + WP_RAD,  98304);
    k_cvtw<<<(573440+255)/256, 256>>>(c1w0, wp + WP_C1G0, 573440);
    k_cvtw<<<(204800+255)/256, 256>>>(c2w0, wp + WP_C2G0, 204800);
    k_prepw<<<(256*512+255)/256, 256>>>(c1w1, wp + WP_C1M1, 256, 512);
    k_prepw<<<(192*384+255)/256, 256>>>(c1w2, wp + WP_C1M2, 192, 384);
    k_prepw<<<(512*256+255)/256, 256>>>(c2w1, wp + WP_C2M1, 512, 256);
    k_prepw<<<(384*192+255)/256, 256>>>(c2w2, wp + WP_C2M2, 384, 192);

    k_radial<<<512, 64>>>(ed, rw1, rb1, rg1, rbe1, rw2, rb2, rg2, rbe2, hid);
    k_gemm_h<<<dim3(MB, 12), 256, GH_SMEM>>>(hid, 64, wp + WP_RAD, rb3, rad, 1536, NE, 1536, 64);
    k_wigner<<<NE, 128>>>(x, ei, wig, rad, sm);
    // conv1
    k_gemm_h<<<dim3(MB, 7), 256, GH_SMEM>>>(sm, 2432, wp + WP_C1G0, c1b0, tmp0, 896, NE, 896, 640);
    k_gemm_h<<<dim3(MB, 4), 256, GH_SMEM>>>(sm+640,  2432, wp + WP_C1M1, nullptr, h1+320, 1216, NE, 512, 1024);
    k_gemm_h<<<dim3(MB, 3), 256, GH_SMEM>>>(sm+1664, 2432, wp + WP_C1M2, nullptr, h1+832, 1216, NE, 384, 768);
    // grid nonlinearity
    k_grid<<<NE/2, 128>>>(tmp0, h1, tgr, fgr, h2);
    // conv2
    k_gemm_h<<<dim3(MB, 5), 256, GH_SMEM>>>(h2, 1216, wp + WP_C2G0, c2b0, h3, 2432, NE, 640, 320);
    k_gemm_h<<<dim3(MB, 8), 256, GH_SMEM>>>(h2+320, 1216, wp + WP_C2M1, nullptr, h3+640,  2432, NE, 1024, 512);
    k_gemm_h<<<dim3(MB, 6), 256, GH_SMEM>>>(h2+832, 1216, wp + WP_C2M2, nullptr, h3+1664, 2432, NE, 768, 384);
    // attention
    k_alpha1<<<NE, 256>>>(tmp0, ei, alng, alnb, adot, alf, amax);
    k_alpha2<<<(NE*8 + 255)/256, 256>>>(alf, ei, amax, den);
    k_attn<<<NE, 128>>>(h3, winv, alf, den, ei, node);
    // projection
    k_proj<<<NN*5, 64>>>(node, pw, pb, outp);
}

// round 10
// speedup vs baseline: 2.2326x; 1.0022x over previous
#include <cuda_runtime.h>
#include <cuda_fp16.h>
#include <cuda_bf16.h>
#include <cstdint>

#define NE 20000
#define NN 1000

// permuted row order: m=0 rows(5), +1(4), -1(4), +2(3), -2(3)
__constant__ int c_PERM[19]   = {0,2,6,11,16, 3,7,12,17, 1,5,10,15, 8,13,18, 4,9,14};
__constant__ int c_RADOFF[19] = {0,128,256,384,512, 640,768,896,1024, 640,768,896,1024,
                                 1152,1280,1408, 1152,1280,1408};

// ----------------- scratch (__device__ globals; no runtime alloc) -----------
__device__ __align__(16) __half g_hid [(size_t)NE*64];    // fp16 activations
__device__ __align__(16) float  g_rad [(size_t)NE*1536];
__device__ __align__(16) __half g_sm  [(size_t)NE*2432];  // wigner out (fp16)
__device__ __align__(16) float  g_tmp0[(size_t)NE*896];   // conv1 gemm0 out (alpha|gate|m0)
__device__ __align__(16) float  g_h1  [(size_t)NE*1216];  // conv1 out rows 5..18 (64/row)
__device__ __align__(16) __half g_h2  [(size_t)NE*1216];  // grid-stage out (fp16)
__device__ __align__(16) float  g_h3  [(size_t)NE*2432];  // conv2 out (19x128 permuted)
__device__ __align__(16) float  g_alf [(size_t)NE*8];
__device__ unsigned int         g_amax[NN*8];
__device__ float                g_den [NN*8];
__device__ __align__(16) float  g_node[(size_t)NN*3200];
// fp16-prepped weights (plain + complex-expanded), element offsets below
__device__ __align__(16) __half g_wp [2514944];

// offsets into g_wp (element counts)
#define WP_RAD   0
#define WP_C1G0  98304
#define WP_C1M1  671744
#define WP_C1M2  1196032
#define WP_C2G0  1490944
#define WP_C2M1  1695744
#define WP_C2M2  2220032

// ----------------- helpers --------------------------------------------------
__device__ __forceinline__ float sigmoidf_(float x){ return 1.f/(1.f+__expf(-x)); }
__device__ __forceinline__ float siluf_(float x){ return x*sigmoidf_(x); }
__device__ __forceinline__ float slrelu_(float x){ return 0.6f*x + 0.4f*x*(2.f*sigmoidf_(x)-1.f); }

// m16n8k16 fp16 mma, fp32 accumulate
__device__ __forceinline__ void mma16h(float* d, const unsigned* a, const unsigned* b){
    asm("mma.sync.aligned.m16n8k16.row.col.f32.f16.f16.f32 "
        "{%0,%1,%2,%3}, {%4,%5,%6,%7}, {%8,%9}, {%0,%1,%2,%3};"
        : "+f"(d[0]), "+f"(d[1]), "+f"(d[2]), "+f"(d[3])
        : "r"(a[0]), "r"(a[1]), "r"(a[2]), "r"(a[3]), "r"(b[0]), "r"(b[1]));
}

// reduce over 64 threads (2 warps), blockDim==64
__device__ __forceinline__ float red64(float v, float* sbuf, int t){
    #pragma unroll
    for (int o=16;o;o>>=1) v += __shfl_xor_sync(0xffffffffu, v, o);
    if ((t&31)==0) sbuf[t>>5] = v;
    __syncthreads();
    float r = sbuf[0]+sbuf[1];
    __syncthreads();
    return r;
}

// ----------------- init -----------------------------------------------------
__global__ void k_init(float* node, unsigned int* amax, float* den){
    int i = blockIdx.x*256 + threadIdx.x;
    if (i < NN*3200) node[i] = 0.f;
    if (i < NN*8) { amax[i] = 0u; den[i] = 0.f; }
}

// ----------------- weight prep ----------------------------------------------
__global__ void k_cvtw(const float* __restrict__ w, __half* __restrict__ o, int n){
    int i = blockIdx.x*256 + threadIdx.x;
    if (i < n) o[i] = __float2half_rn(w[i]);
}
// complex: w[(2N)xK] (rows 0..N-1 = Wr, N..2N-1 = Wi) ->
// wp[(2N)x(2K)]: row n = [Wr[n] | -Wi[n]], row N+n = [Wi[n] | Wr[n]]
__global__ void k_prepw(const float* __restrict__ w, __half* __restrict__ wp, int N, int K){
    int i = blockIdx.x*256 + threadIdx.x;
    if (i >= N*K) return;
    int n = i / K, k = i % K;
    float wr = w[(size_t)n*K + k];
    float wi = w[(size_t)(N+n)*K + k];
    size_t row0 = (size_t)n*2*K, row1 = (size_t)(N+n)*2*K;
    wp[row0 + k]     = __float2half_rn(wr);
    wp[row0 + K + k] = __float2half_rn(-wi);
    wp[row1 + k]     = __float2half_rn(wi);
    wp[row1 + K + k] = __float2half_rn(wr);
}

// ----------------- radial layers 1+2 (LN + silu) ----------------------------
__global__ void k_radial(const float* __restrict__ ed,
                         const float* __restrict__ w1, const float* __restrict__ b1,
                         const float* __restrict__ g1, const float* __restrict__ be1,
                         const float* __restrict__ w2, const float* __restrict__ b2,
                         const float* __restrict__ g2, const float* __restrict__ be2,
                         __half* __restrict__ outp)
{
    __shared__ float w1t[64*64], w2t[64*64];
    __shared__ float xin[64], hmid[64];
    __shared__ float sbuf[2];
    int t = threadIdx.x; // 64
    for (int i = t; i < 4096; i += 64) {
        int r = i >> 6, c = i & 63;
        w1t[c*64 + r] = w1[i];
        w2t[c*64 + r] = w2[i];
    }
    __syncthreads();
    for (int e = blockIdx.x; e < NE; e += gridDim.x) {
        xin[t] = ed[(size_t)e*64 + t];
        __syncthreads();
        float acc = b1[t];
        #pragma unroll 8
        for (int k = 0; k < 64; k++) acc += xin[k]*w1t[k*64+t];
        float mu = red64(acc, sbuf, t) * (1.f/64.f);
        float d = acc - mu;
        float var = red64(d*d, sbuf, t) * (1.f/64.f);
        float v = d*rsqrtf(var+1e-5f)*g1[t] + be1[t];
        hmid[t] = siluf_(v);
        __syncthreads();
        acc = b2[t];
        #pragma unroll 8
        for (int k = 0; k < 64; k++) acc += hmid[k]*w2t[k*64+t];
        mu = red64(acc, sbuf, t) * (1.f/64.f);
        d = acc - mu;
        var = red64(d*d, sbuf, t) * (1.f/64.f);
        v = d*rsqrtf(var+1e-5f)*g2[t] + be2[t];
        outp[(size_t)e*64 + t] = __float2half_rn(siluf_(v));
        __syncthreads();
    }
}

// ======= fp16 tensor-core GEMM: C[M,N] = A[M,K] @ W[N,K]^T (+bias) ==========
// A and W both fp16 in gmem; CTA tile 256x128, 8 warps (4x2), warp m64n64, BK=16.
// Double-buffered with register prefetch. N%128==0, K%16==0 required.
#define GH_ASTRIDE 264
#define GH_BSTRIDE 136
#define GH_BOFF    (2*8*GH_ASTRIDE)
#define GH_SMEM    ((2*8*GH_ASTRIDE + 2*8*GH_BSTRIDE)*4)

__global__ void __launch_bounds__(256) k_gemm_h(
        const __half* __restrict__ A, int lda,
        const __half* __restrict__ W,
        const float* __restrict__ bias,
        float* __restrict__ C, int ldc, int M, int N, int K)
{
    extern __shared__ __align__(16) unsigned smemu[];
    unsigned (*As2)[8][GH_ASTRIDE] = (unsigned(*)[8][GH_ASTRIDE])smemu;
    unsigned (*Bs2)[8][GH_BSTRIDE] = (unsigned(*)[8][GH_BSTRIDE])(smemu + GH_BOFF);
    const int tid = threadIdx.x;
    const int bm = blockIdx.x*256, bn = blockIdx.y*128;
    const int wid = tid >> 5, lane = tid & 31;
    const int wm = wid & 3, wn = wid >> 2;        // 4 x 2 warps, warp tile m64 n64
    const int g = lane >> 2, q = lane & 3;
    const int srow = tid >> 2, sq4 = tid & 3;     // staging

    float acc[4][8][4];
    #pragma unroll
    for (int i=0;i<4;i++)
        #pragma unroll
        for (int j=0;j<8;j++)
            #pragma unroll
            for (int r=0;r<4;r++) acc[i][j][r] = 0.f;

    #define HSTAGE_A(buf, k0) { \
        _Pragma("unroll") \
        for (int i = 0; i < 4; i++) { \
            int row = srow + 64*i; \
            uint2 v = make_uint2(0u, 0u); \
            if (bm + row < M) v = *(const uint2*)(A + (size_t)(bm+row)*lda + (k0) + sq4*4); \
            As2[buf][sq4*2+0][row] = v.x; \
            As2[buf][sq4*2+1][row] = v.y; \
        } }
    #define HSTAGE_B(buf, k0) { \
        _Pragma("unroll") \
        for (int i = 0; i < 2; i++) { \
            int row = srow + 64*i; \
            uint2 v = *(const uint2*)(W + (size_t)(bn+row)*K + (k0) + sq4*4); \
            Bs2[buf][sq4*2+0][row] = v.x; \
            Bs2[buf][sq4*2+1][row] = v.y; \
        } }

    HSTAGE_A(0, 0)
    HSTAGE_B(0, 0)
    __syncthreads();

    const int nit = K >> 4;
    int buf = 0;
    for (int it = 0; it < nit; it++) {
        // register prefetch of next tile
        uint2 pa[4], pb[2];
        const bool more = (it + 1 < nit);
        if (more) {
            int k0 = (it + 1) << 4;
            #pragma unroll
            for (int i = 0; i < 4; i++) {
                int row = srow + 64*i;
                pa[i] = make_uint2(0u, 0u);
                if (bm + row < M) pa[i] = *(const uint2*)(A + (size_t)(bm+row)*lda + k0 + sq4*4);
            }
            #pragma unroll
            for (int i = 0; i < 2; i++) {
                int row = srow + 64*i;
                pb[i] = *(const uint2*)(W + (size_t)(bn+row)*K + k0 + sq4*4);
            }
        }
        // MMA on current buffer: one k16 pass
        {
            unsigned af[4][4];
            #pragma unroll
            for (int mt=0; mt<4; mt++){
                int mb = wm*64 + mt*16;
                af[mt][0] = As2[buf][q  ][mb+g  ];
                af[mt][1] = As2[buf][q  ][mb+g+8];
                af[mt][2] = As2[buf][q+4][mb+g  ];
                af[mt][3] = As2[buf][q+4][mb+g+8];
            }
            unsigned bf[8][2];
            #pragma unroll
            for (int nt=0; nt<8; nt++){
                int nb = wn*64 + nt*8;
                bf[nt][0] = Bs2[buf][q  ][nb+g];
                bf[nt][1] = Bs2[buf][q+4][nb+g];
            }
            #pragma unroll
            for (int mt=0; mt<4; mt++)
                #pragma unroll
                for (int nt=0; nt<8; nt++)
                    mma16h(acc[mt][nt], af[mt], bf[nt]);
        }
        if (more) {
            int nb2 = buf ^ 1;
            #pragma unroll
            for (int i = 0; i < 4; i++) {
                int row = srow + 64*i;
                As2[nb2][sq4*2+0][row] = pa[i].x;
                As2[nb2][sq4*2+1][row] = pa[i].y;
            }
            #pragma unroll
            for (int i = 0; i < 2; i++) {
                int row = srow + 64*i;
                Bs2[nb2][sq4*2+0][row] = pb[i].x;
                Bs2[nb2][sq4*2+1][row] = pb[i].y;
            }
            __syncthreads();
            buf = nb2;
        }
    }
    // epilogue
    #pragma unroll
    for (int nt=0; nt<8; nt++) {
        int c = bn + wn*64 + nt*8 + q*2;
        float2 bv = make_float2(0.f, 0.f);
        if (bias) bv = *(const float2*)(bias + c);
        #pragma unroll
        for (int mt=0; mt<4; mt++) {
            int r0 = bm + wm*64 + mt*16 + g;
            if (r0 < M) {
                float2 o = make_float2(acc[mt][nt][0]+bv.x, acc[mt][nt][1]+bv.y);
                *(float2*)(C + (size_t)r0*ldc + c) = o;
            }
            if (r0 + 8 < M) {
                float2 o = make_float2(acc[mt][nt][2]+bv.x, acc[mt][nt][3]+bv.y);
                *(float2*)(C + (size_t)(r0+8)*ldc + c) = o;
            }
        }
    }
}

// ---------- wigner: msg = perm(wigner @ [x_src|x_dst]) * rad (fp16 out) -----
__global__ void k_wigner(const float* __restrict__ x, const int* __restrict__ ei,
                         const float* __restrict__ wig, const float* __restrict__ rad,
                         __half* __restrict__ sm)
{
    __shared__ float msg[25][128];
    __shared__ float wg[19][25];
    int e = blockIdx.x;
    int t = threadIdx.x; // 128
    int src = ei[e], dst = ei[NE + e];
    const float* xs = x + (size_t)src*1600;
    const float* xd = x + (size_t)dst*1600;
    int c = t & 63;
    if (t < 64) { for (int j=0;j<25;j++) msg[j][t] = xs[j*64+c]; }
    else        { for (int j=0;j<25;j++) msg[j][t] = xd[j*64+c]; }
    for (int i = t; i < 475; i += 128) {
        int p = i/25, j = i%25;
        wg[p][j] = wig[(size_t)e*475 + (size_t)c_PERM[p]*25 + j];
    }
    __syncthreads();
    const float* re = rad + (size_t)e*1536;
    __half* so = sm + (size_t)e*2432;
    #pragma unroll
    for (int p = 0; p < 19; p++) {
        float acc = 0.f;
        #pragma unroll
        for (int j = 0; j < 25; j++) acc += wg[p][j]*msg[j][t];
        so[p*128 + t] = __float2half_rn(acc * re[c_RADOFF[p] + t]);
    }
}

// ---------- grid stage: silu-gated S2 pointwise (fp16 out) ------------------
__global__ void k_grid(const float* __restrict__ tmp0, const float* __restrict__ h1,
                       const float* __restrict__ tgrid, const float* __restrict__ fgrid,
                       __half* __restrict__ h2)
{
    __shared__ float tg[100][20];
    __shared__ float fg[100][20];
    __shared__ float h[2][19][64];
    int t = threadIdx.x; // 128
    for (int i = t; i < 1900; i += 128) {
        int ba = i / 19, p = i % 19;
        tg[ba][p] = tgrid[ba*19 + c_PERM[p]];
        fg[ba][p] = fgrid[ba*19 + c_PERM[p]];
    }
    int el = t >> 6, c = t & 63;
    int e = blockIdx.x*2 + el;
    const float* t0 = tmp0 + (size_t)e*896;
    #pragma unroll
    for (int p = 0; p < 5; p++) h[el][p][c] = t0[576 + p*64 + c];
    const float* hh = h1 + (size_t)e*1216;
    #pragma unroll
    for (int p = 5; p < 19; p++) h[el][p][c] = hh[p*64 + c];
    __syncthreads();
    float s2[19];
    #pragma unroll
    for (int p=0;p<19;p++) s2[p]=0.f;
    for (int ba = 0; ba < 100; ba++) {
        float g = 0.f;
        #pragma unroll
        for (int p = 0; p < 19; p++) g += tg[ba][p]*h[el][p][c];
        g = siluf_(g);
        #pragma unroll
        for (int p = 0; p < 19; p++) s2[p] += fg[ba][p]*g;
    }
    __half* o = h2 + (size_t)e*1216;
    o[c] = __float2half_rn(siluf_(t0[512 + c]));    // row 0 := silu(gate)
    #pragma unroll
    for (int p = 1; p < 19; p++) o[p*64 + c] = __float2half_rn(s2[p]);
}

// ---------- alpha: LN + smooth-leaky-relu + dot, atomicMax ------------------
__global__ void k_alpha1(const float* __restrict__ tmp0, const int* __restrict__ ei,
                         const float* __restrict__ lng, const float* __restrict__ lnb,
                         const float* __restrict__ adot,
                         float* __restrict__ alpha, unsigned int* __restrict__ amax)
{
    int e = blockIdx.x;
    int w = threadIdx.x >> 5, lane = threadIdx.x & 31; // 8 warps = 8 heads
    const float* a = tmp0 + (size_t)e*896 + w*64;
    float v0 = a[lane], v1 = a[lane+32];
    float s = v0+v1;
    #pragma unroll
    for (int o=16;o;o>>=1) s += __shfl_xor_sync(0xffffffffu, s, o);
    float mu = s * (1.f/64.f);
    float d0=v0-mu, d1=v1-mu;
    float q = d0*d0+d1*d1;
    #pragma unroll
    for (int o=16;o;o>>=1) q += __shfl_xor_sync(0xffffffffu, q, o);
    float rstd = rsqrtf(q*(1.f/64.f) + 1e-5f);
    float x0 = slrelu_(d0*rstd*lng[lane]+lnb[lane]);
    float x1 = slrelu_(d1*rstd*lng[lane+32]+lnb[lane+32]);
    float p = x0*adot[w*64+lane] + x1*adot[w*64+lane+32];
    #pragma unroll
    for (int o=16;o;o>>=1) p += __shfl_xor_sync(0xffffffffu, p, o);
    if (lane == 0) {
        alpha[e*8+w] = p;
        int dst = ei[NE + e];
        unsigned int enc = __float_as_uint(p);
        enc = (enc & 0x80000000u) ? ~enc : (enc | 0x80000000u);
        atomicMax(&amax[dst*8+w], enc);
    }
}

__global__ void k_alpha2(float* __restrict__ alpha, const int* __restrict__ ei,
                         const unsigned int* __restrict__ amax, float* __restrict__ den)
{
    int i = blockIdx.x*256 + threadIdx.x;
    if (i >= NE*8) return;
    int e = i >> 3, h = i & 7;
    int dst = ei[NE + e];
    unsigned int u = amax[dst*8+h];
    float m = (u & 0x80000000u) ? __uint_as_float(u & 0x7FFFFFFFu) : __uint_as_float(~u);
    float ex = __expf(alpha[i] - m);
    alpha[i] = ex;
    atomicAdd(&den[dst*8+h], ex);
}

// ---------- attention weight + wigner_inv + segment-sum ---------------------
__global__ void k_attn(const float* __restrict__ h3, const float* __restrict__ winv,
                       const float* __restrict__ alpha, const float* __restrict__ den,
                       const int* __restrict__ ei, float* __restrict__ node)
{
    __shared__ float m[19][128];
    __shared__ float wi[25][20];
    __shared__ float wt[8];
    int e = blockIdx.x, t = threadIdx.x; // 128
    int dst = ei[NE + e];
    if (t < 8) wt[t] = alpha[e*8+t] / (den[dst*8+t] + 1e-16f);
    for (int i = t; i < 475; i += 128) {
        int r = i/19, p = i%19;
        wi[r][p] = winv[(size_t)e*475 + r*19 + c_PERM[p]];
    }
    __syncthreads();
    const float* hh = h3 + (size_t)e*2432;
    float w = wt[t >> 4];
    #pragma unroll
    for (int p = 0; p < 19; p++) m[p][t] = hh[p*128 + t] * w;
    __syncthreads();
    float* no = node + (size_t)dst*3200;
    #pragma unroll
    for (int r = 0; r < 25; r++) {
        float acc = 0.f;
        #pragma unroll
        for (int p = 0; p < 19; p++) acc += wi[r][p]*m[p][t];
        atomicAdd(&no[r*128 + t], acc);
    }
}

// ---------- output projection ----------------------------------------------
__global__ void k_proj(const float* __restrict__ node, const float* __restrict__ pw,
                       const float* __restrict__ pb, float* __restrict__ outp)
{
    __shared__ float wt[128*65];
    int bid = blockIdx.x;      // n*5 + l
    int n = bid / 5, l = bid % 5;
    int t = threadIdx.x;       // 64
    for (int i = t; i < 8192; i += 64) {
        int o = i >> 7, c = i & 127;
        wt[c*65 + o] = pw[l*8192 + i];
    }
    __syncthreads();
    int i0 = l*l, i1 = (l+1)*(l+1);
    for (int i = i0; i < i1; i++) {
        const float* nr = node + (size_t)n*3200 + i*128;
        float acc = (i == 0) ? pb[t] : 0.f;
        #pragma unroll 8
        for (int c = 0; c < 128; c++) acc += nr[c] * wt[c*65 + t];
        outp[(size_t)n*1600 + i*64 + t] = acc;
    }
}

// ----------------------------------------------------------------------------
extern "C" void kernel_launch(void* const* d_in, const int* in_sizes, int n_in,
                              void* d_out, int out_size)
{
    const float* x    = (const float*)d_in[0];
    const float* ed   = (const float*)d_in[1];
    const int*   ei   = (const int*)  d_in[2];
    const float* wig  = (const float*)d_in[3];
    const float* winv = (const float*)d_in[4];
    const float* tgr  = (const float*)d_in[5];
    const float* fgr  = (const float*)d_in[6];
    const float* rw1  = (const float*)d_in[7];
    const float* rb1  = (const float*)d_in[8];
    const float* rg1  = (const float*)d_in[9];
    const float* rbe1 = (const float*)d_in[10];
    const float* rw2  = (const float*)d_in[11];
    const float* rb2  = (const float*)d_in[12];
    const float* rg2  = (const float*)d_in[13];
    const float* rbe2 = (const float*)d_in[14];
    const float* rw3  = (const float*)d_in[15];
    const float* rb3  = (const float*)d_in[16];
    const float* c1w0 = (const float*)d_in[17];
    const float* c1b0 = (const float*)d_in[18];
    const float* c1w1 = (const float*)d_in[19];
    const float* c1w2 = (const float*)d_in[20];
    const float* c2w0 = (const float*)d_in[21];
    const float* c2b0 = (const float*)d_in[22];
    const float* c2w1 = (const float*)d_in[23];
    const float* c2w2 = (const float*)d_in[24];
    const float* alng = (const float*)d_in[25];
    const float* alnb = (const float*)d_in[26];
    const float* adot = (const float*)d_in[27];
    const float* pw   = (const float*)d_in[28];
    const float* pb   = (const float*)d_in[29];
    float* outp = (float*)d_out;

    void* p;
    cudaGetSymbolAddress(&p, g_hid);  __half* hid = (__half*)p;
    cudaGetSymbolAddress(&p, g_rad);  float* rad  = (float*)p;
    cudaGetSymbolAddress(&p, g_sm);   __half* sm  = (__half*)p;
    cudaGetSymbolAddress(&p, g_tmp0); float* tmp0 = (float*)p;
    cudaGetSymbolAddress(&p, g_h1);   float* h1   = (float*)p;
    cudaGetSymbolAddress(&p, g_h2);   __half* h2  = (__half*)p;
    cudaGetSymbolAddress(&p, g_h3);   float* h3   = (float*)p;
    cudaGetSymbolAddress(&p, g_alf);  float* alf  = (float*)p;
    cudaGetSymbolAddress(&p, g_amax); unsigned int* amax = (unsigned int*)p;
    cudaGetSymbolAddress(&p, g_den);  float* den  = (float*)p;
    cudaGetSymbolAddress(&p, g_node); float* node = (float*)p;
    cudaGetSymbolAddress(&p, g_wp);   __half* wp  = (__half*)p;

    cudaFuncSetAttribute(k_gemm_h, cudaFuncAttributeMaxDynamicSharedMemorySize, GH_SMEM);

    const int MB = (NE + 255) / 256;   // 79

    k_init<<<(NN*3200 + 255)/256, 256>>>(node, amax, den);

    // weight prep (fp16 round; complex weights expanded to real form)
    k_cvtw<<<(98304+255)/256, 256>>>(rw3,  wp + WP_RAD,  98304);
    k_cvtw<<<(573440+255)/256, 256>>>(c1w0, wp + WP_C1G0, 573440);
    k_cvtw<<<(204800+255)/256, 256>>>(c2w0, wp + WP_C2G0, 204800);
    k_prepw<<<(256*512+255)/256, 256>>>(c1w1, wp + WP_C1M1, 256, 512);
    k_prepw<<<(192*384+255)/256, 256>>>(c1w2, wp + WP_C1M2, 192, 384);
    k_prepw<<<(512*256+255)/256, 256>>>(c2w1, wp + WP_C2M1, 512, 256);
    k_prepw<<<(384*192+255)/256, 256>>>(c2w2, wp + WP_C2M2, 384, 192);

    k_radial<<<512, 64>>>(ed, rw1, rb1, rg1, rbe1, rw2, rb2, rg2, rbe2, hid);
    k_gemm_h<<<dim3(MB, 12), 256, GH_SMEM>>>(hid, 64, wp + WP_RAD, rb3, rad, 1536, NE, 1536, 64);
    k_wigner<<<NE, 128>>>(x, ei, wig, rad, sm);
    // conv1
    k_gemm_h<<<dim3(MB, 7), 256, GH_SMEM>>>(sm, 2432, wp + WP_C1G0, c1b0, tmp0, 896, NE, 896, 640);
    k_gemm_h<<<dim3(MB, 4), 256, GH_SMEM>>>(sm+640,  2432, wp + WP_C1M1, nullptr, h1+320, 1216, NE, 512, 1024);
    k_gemm_h<<<dim3(MB, 3), 256, GH_SMEM>>>(sm+1664, 2432, wp + WP_C1M2, nullptr, h1+832, 1216, NE, 384, 768);
    // grid nonlinearity
    k_grid<<<NE/2, 128>>>(tmp0, h1, tgr, fgr, h2);
    // conv2
    k_gemm_h<<<dim3(MB, 5), 256, GH_SMEM>>>(h2, 1216, wp + WP_C2G0, c2b0, h3, 2432, NE, 640, 320);
    k_gemm_h<<<dim3(MB, 8), 256, GH_SMEM>>>(h2+320, 1216, wp + WP_C2M1, nullptr, h3+640,  2432, NE, 1024, 512);
    k_gemm_h<<<dim3(MB, 6), 256, GH_SMEM>>>(h2+832, 1216, wp + WP_C2M2, nullptr, h3+1664, 2432, NE, 768, 384);
    // attention
    k_alpha1<<<NE, 256>>>(tmp0, ei, alng, alnb, adot, alf, amax);
    k_alpha2<<<(NE*8 + 255)/256, 256>>>(alf, ei, amax, den);
    k_attn<<<NE, 128>>>(h3, winv, alf, den, ei, node);
    // projection
    k_proj<<<NN*5, 64>>>(node, pw, pb, outp);
}